// round 11
// baseline (speedup 1.0000x reference)
#include <cuda_runtime.h>
#include <cuda_bf16.h>
#include <math.h>

// Problem constants (fixed shapes)
#define Dd 1024
#define Aa 16
#define Cc 8
#define DCc 64
#define CDd 512      // C*dc
#define E2 128       // 2*dc
#define TB 32        // tokens per CTA in token_kernel
#define NMAX 32768

// -------- device scratch (no allocations allowed) --------
__device__ __align__(16) float g_an[Aa * Dd];                  // l2-normalized anchors
__device__ __align__(16) float g_gatesig[Dd];                  // sigmoid(gate)
__device__ __align__(16) uint4 g_Yfrag[(NMAX / 16) * 32 * 32]; // 32 MB: Y as HMMA A-fragments
__device__ __align__(16) uint2 g_WpFrag[128 * 32 * 32];        // 1 MB: Wp as HMMA B-fragments
__device__ __align__(16) uint2 g_W2frag[Cc * 8 * 8 * 32];      // W2 in HMMA B-fragment layout
__device__ __align__(16) uint2 g_AnFrag[64 * 2 * 32];          // anchors in HMMA B-fragment layout

__device__ __forceinline__ float wsum(float v) {
#pragma unroll
    for (int o = 16; o; o >>= 1) v += __shfl_xor_sync(0xffffffffu, v, o);
    return v;
}

// -------- tensor-core helpers --------
__device__ __forceinline__ void ldm_x4(unsigned* r, unsigned addr) {
    asm volatile("ldmatrix.sync.aligned.m8n8.x4.shared.b16 {%0,%1,%2,%3}, [%4];"
        : "=r"(r[0]), "=r"(r[1]), "=r"(r[2]), "=r"(r[3]) : "r"(addr));
}
__device__ __forceinline__ void mma_bf16(float* d, const unsigned* a, unsigned b0, unsigned b1) {
    asm volatile("mma.sync.aligned.m16n8k16.row.col.f32.bf16.bf16.f32 "
        "{%0,%1,%2,%3}, {%4,%5,%6,%7}, {%8,%9}, {%0,%1,%2,%3};"
        : "+f"(d[0]), "+f"(d[1]), "+f"(d[2]), "+f"(d[3])
        : "r"(a[0]), "r"(a[1]), "r"(a[2]), "r"(a[3]), "r"(b0), "r"(b1));
}

__device__ __forceinline__ unsigned pk_bf16x2(float lo, float hi) {
    __nv_bfloat162 t = __floats2bfloat162_rn(lo, hi);
    return *reinterpret_cast<unsigned*>(&t);
}

// ================= K0: prep anchors + gate + WpFrag + W2 fragments =================
__global__ void prep_kernel(const float* __restrict__ anchors, const float* __restrict__ gate,
                            const float* __restrict__ Wp, const float* __restrict__ W2) {
    int tid = threadIdx.x, lane = tid & 31, wid = tid >> 5;
    __shared__ float red[8];
    if (blockIdx.x < Aa) {
        int j = blockIdx.x;
        float4 v = *(const float4*)(anchors + j * Dd + tid * 4);
        float s = v.x * v.x + v.y * v.y + v.z * v.z + v.w * v.w;
        s = wsum(s);
        if (lane == 0) red[wid] = s;
        __syncthreads();
        if (wid == 0) {
            float t = (lane < 8) ? red[lane] : 0.f;
            t = wsum(t);
            if (lane == 0) red[0] = t;
        }
        __syncthreads();
        float inv = 1.0f / fmaxf(sqrtf(red[0]), 1e-12f);
        float4 o = make_float4(v.x * inv, v.y * inv, v.z * inv, v.w * inv);
        *(float4*)(g_an + j * Dd + tid * 4) = o;
    } else if (blockIdx.x == Aa) {
        for (int i = tid; i < Dd; i += 256)
            g_gatesig[i] = 1.0f / (1.0f + expf(-gate[i]));
    } else if (blockIdx.x < Aa + 1 + 64) {
        // Wp -> HMMA B-fragment layout: 64 blocks, each 2 n8-tiles (2048 entries)
        int base = (blockIdx.x - Aa - 1) * 2048;
        for (int j = tid; j < 2048; j += 256) {
            int e = base + j;
            int ln = e & 31;
            int ks = (e >> 5) & 31;
            int ntg = e >> 10;                  // n8-tile 0..127
            int N = ntg * 8 + (ln >> 2);
            int e0 = ks * 16 + 2 * (ln & 3);
            uint2 v;
            v.x = pk_bf16x2(Wp[(long)e0 * Dd + N],       Wp[(long)(e0 + 1) * Dd + N]);
            v.y = pk_bf16x2(Wp[(long)(e0 + 8) * Dd + N], Wp[(long)(e0 + 9) * Dd + N]);
            g_WpFrag[e] = v;
        }
    } else {
        // W2 -> HMMA B-fragment layout, one block per comp
        int k = blockIdx.x - (Aa + 1 + 64);
        const float* w = W2 + (long)k * E2 * DCc;   // [128][64]
        for (int idx = tid; idx < 2048; idx += 256) {
            int kt = idx >> 8;
            int rem = idx & 255;
            int nt = rem >> 5;
            int ln = rem & 31;
            int q = ln & 3, gg = ln >> 2;
            int N = nt * 8 + gg;
            int e0 = kt * 16 + 2 * q;
            uint2 val;
            val.x = pk_bf16x2(w[e0 * 64 + N],       w[(e0 + 1) * 64 + N]);
            val.y = pk_bf16x2(w[(e0 + 8) * 64 + N], w[(e0 + 9) * 64 + N]);
            g_W2frag[((k * 8 + kt) * 8 + nt) * 32 + ln] = val;
        }
    }
}

// ================= K0b: anchor B-fragment table (needs normalized g_an) =================
__global__ void prep2_kernel() {
    int idx = blockIdx.x * 256 + threadIdx.x;   // grid 4 x 256 = 1024
    for (int e = idx; e < 64 * 2 * 32; e += 1024) {
        int ln = e & 31, nt = (e >> 5) & 1, kt = e >> 6;
        int q = ln & 3, gg = ln >> 2;
        int n = nt * 8 + gg;
        int k0 = kt * 16 + 2 * q;
        uint2 val;
        val.x = pk_bf16x2(g_an[n * Dd + k0],     g_an[n * Dd + k0 + 1]);
        val.y = pk_bf16x2(g_an[n * Dd + k0 + 8], g_an[n * Dd + k0 + 9]);
        g_AnFrag[(kt * 2 + nt) * 32 + ln] = val;
    }
}

// ================= K1: LN/L2 -> bf16 H -> HMMA dots -> warp-per-comp HMMA MLP =================
#define OFF_H    0        // 16384 floats = 64 KB: H tile 32 x 1024 bf16 (row stride 2048 B, swizzled)
#define OFF_W1   16384
#define OFF_B1   18432
#define OFF_B2   19456
#define OFF_CG   19968
#define OFF_CB   20480
#define OFF_TRI  20992
#define OFF_LNG  21504
#define OFF_LNB  22528
#define OFF_PART 23552
#define SM_FLOATS 25600   // 102400 bytes

__global__ void __launch_bounds__(256, 2)
token_kernel(const float* __restrict__ x,
             const float* __restrict__ ln_g, const float* __restrict__ ln_b,
             const float* __restrict__ W1, const float* __restrict__ b1,
             const float* __restrict__ b2, const float* __restrict__ cg,
             const float* __restrict__ cb)
{
    extern __shared__ float sm[];
    const unsigned sbase = (unsigned)__cvta_generic_to_shared(sm);
    const int tid = threadIdx.x, lane = tid & 31, wid = tid >> 5;

    for (int t = tid; t < 512; t += 256)
        *(float4*)&sm[OFF_W1 + t * 4] = *(const float4*)&W1[t * 4];
    *(float4*)&sm[OFF_B1 + tid * 4] = *(const float4*)&b1[tid * 4];
    if (tid < 128) {
        *(float4*)&sm[OFF_B2 + tid * 4] = *(const float4*)&b2[tid * 4];
        *(float4*)&sm[OFF_CG + tid * 4] = *(const float4*)&cg[tid * 4];
        *(float4*)&sm[OFF_CB + tid * 4] = *(const float4*)&cb[tid * 4];
    }
    *(float4*)&sm[OFF_LNG + tid * 4] = *(const float4*)&ln_g[tid * 4];
    *(float4*)&sm[OFF_LNB + tid * 4] = *(const float4*)&ln_b[tid * 4];
    __syncthreads();

    const long base_tok = (long)blockIdx.x * TB;

    // ---------- Phase A: 2 tokens per warp per round; fused sum+sumsq ----------
    for (int r = 0; r < 2; ++r) {
        const int na = r * 16 + wid * 2;           // tokens na, na+1
        const float* xra = x + (base_tok + na) * (long)Dd;
        const float* xrb = xra + Dd;
        float va[32], vb[32];
#pragma unroll
        for (int q = 0; q < 8; ++q) {
            float4 ta = *(const float4*)(xra + q * 128 + lane * 4);
            float4 tb = *(const float4*)(xrb + q * 128 + lane * 4);
            va[q*4+0] = ta.x; va[q*4+1] = ta.y; va[q*4+2] = ta.z; va[q*4+3] = ta.w;
            vb[q*4+0] = tb.x; vb[q*4+1] = tb.y; vb[q*4+2] = tb.z; vb[q*4+3] = tb.w;
        }
        float sa = 0.f, qa = 0.f, sb = 0.f, qb = 0.f;
#pragma unroll
        for (int i = 0; i < 32; ++i) {
            sa += va[i]; qa = fmaf(va[i], va[i], qa);
            sb += vb[i]; qb = fmaf(vb[i], vb[i], qb);
        }
#pragma unroll
        for (int o = 16; o; o >>= 1) {
            sa += __shfl_xor_sync(0xffffffffu, sa, o);
            sb += __shfl_xor_sync(0xffffffffu, sb, o);
            qa += __shfl_xor_sync(0xffffffffu, qa, o);
            qb += __shfl_xor_sync(0xffffffffu, qb, o);
        }
        const float mua = sa * (1.0f / Dd), mub = sb * (1.0f / Dd);
        const float rsa = rsqrtf(fmaxf(qa * (1.0f / Dd) - mua * mua, 0.f) + 1e-5f);
        const float rsb = rsqrtf(fmaxf(qb * (1.0f / Dd) - mub * mub, 0.f) + 1e-5f);

        float n2a = 0.f, n2b = 0.f;
#pragma unroll
        for (int q = 0; q < 8; ++q) {
            float4 gv = *(const float4*)&sm[OFF_LNG + q * 128 + lane * 4];
            float4 bv = *(const float4*)&sm[OFF_LNB + q * 128 + lane * 4];
            float a0 = (va[q*4+0] - mua) * rsa * gv.x + bv.x;
            float a1 = (va[q*4+1] - mua) * rsa * gv.y + bv.y;
            float a2 = (va[q*4+2] - mua) * rsa * gv.z + bv.z;
            float a3 = (va[q*4+3] - mua) * rsa * gv.w + bv.w;
            float c0 = (vb[q*4+0] - mub) * rsb * gv.x + bv.x;
            float c1 = (vb[q*4+1] - mub) * rsb * gv.y + bv.y;
            float c2 = (vb[q*4+2] - mub) * rsb * gv.z + bv.z;
            float c3 = (vb[q*4+3] - mub) * rsb * gv.w + bv.w;
            va[q*4+0] = a0; va[q*4+1] = a1; va[q*4+2] = a2; va[q*4+3] = a3;
            vb[q*4+0] = c0; vb[q*4+1] = c1; vb[q*4+2] = c2; vb[q*4+3] = c3;
            n2a += a0*a0 + a1*a1 + a2*a2 + a3*a3;
            n2b += c0*c0 + c1*c1 + c2*c2 + c3*c3;
        }
#pragma unroll
        for (int o = 16; o; o >>= 1) {
            n2a += __shfl_xor_sync(0xffffffffu, n2a, o);
            n2b += __shfl_xor_sync(0xffffffffu, n2b, o);
        }
        const float inva = 1.0f / fmaxf(sqrtf(n2a), 1e-12f);
        const float invb = 1.0f / fmaxf(sqrtf(n2b), 1e-12f);

        char* hra = (char*)sm + na * 2048;
        char* hrb = hra + 2048;
        const unsigned swa = (unsigned)((na & 7) << 4);
        const unsigned swb = (unsigned)(((na + 1) & 7) << 4);
#pragma unroll
        for (int q = 0; q < 8; ++q) {
            unsigned off = (unsigned)(q * 256 + lane * 8);
            *(uint2*)(hra + (off ^ swa)) =
                make_uint2(pk_bf16x2(va[q*4+0]*inva, va[q*4+1]*inva),
                           pk_bf16x2(va[q*4+2]*inva, va[q*4+3]*inva));
            *(uint2*)(hrb + (off ^ swb)) =
                make_uint2(pk_bf16x2(vb[q*4+0]*invb, vb[q*4+1]*invb),
                           pk_bf16x2(vb[q*4+2]*invb, vb[q*4+3]*invb));
        }
    }
    __syncthreads();

    // ---------- Phase A2: tri = 1 - H @ Anchors^T via HMMA ----------
    {
        const int mt = wid & 1;
        const int kq = wid >> 1;
        const int al = lane & 15, ah = lane >> 4;
        const unsigned rowb = (unsigned)(mt * 16 + al);
        const unsigned rowoff = rowb * 2048;
        const unsigned swz = (rowb & 7) << 4;

        float acc[2][4];
#pragma unroll
        for (int nt = 0; nt < 2; ++nt)
#pragma unroll
            for (int c = 0; c < 4; ++c) acc[nt][c] = 0.f;

#pragma unroll
        for (int s = 0; s < 16; ++s) {
            const int kt = kq * 16 + s;
            unsigned afr[4];
            unsigned off = rowoff + (((unsigned)(kt * 32 + ah * 16)) ^ swz);
            ldm_x4(afr, sbase + off);
            uint2 b0 = g_AnFrag[(kt * 2 + 0) * 32 + lane];
            uint2 b1 = g_AnFrag[(kt * 2 + 1) * 32 + lane];
            mma_bf16(acc[0], afr, b0.x, b0.y);
            mma_bf16(acc[1], afr, b1.x, b1.y);
        }
        float* P = &sm[OFF_PART + kq * 512];
        const int r0 = mt * 16 + (lane >> 2);
        const int c0 = 2 * (lane & 3);
        P[r0 * 16 + c0]           = acc[0][0];
        P[r0 * 16 + c0 + 1]       = acc[0][1];
        P[(r0 + 8) * 16 + c0]     = acc[0][2];
        P[(r0 + 8) * 16 + c0 + 1] = acc[0][3];
        P[r0 * 16 + 8 + c0]           = acc[1][0];
        P[r0 * 16 + 8 + c0 + 1]       = acc[1][1];
        P[(r0 + 8) * 16 + 8 + c0]     = acc[1][2];
        P[(r0 + 8) * 16 + 8 + c0 + 1] = acc[1][3];
    }
    __syncthreads();
    for (int t = tid; t < 512; t += 256) {
        float d = sm[OFF_PART + t] + sm[OFF_PART + 512 + t]
                + sm[OFF_PART + 1024 + t] + sm[OFF_PART + 1536 + t];
        sm[OFF_TRI + t] = 1.0f - d;
    }
    __syncthreads();

    // ---------- Phase B: warp w = compartment w; store Y as A-fragments ----------
    {
        const int k = wid;
        const int q = lane & 3, rr = lane >> 2;

        float g00[2], g01[2], g10[2], g11[2];
#pragma unroll
        for (int mt = 0; mt < 2; ++mt) {
            int n0 = mt * 16 + rr;
            g00[mt] = sm[OFF_TRI + n0 * 16 + k];
            g01[mt] = sm[OFF_TRI + n0 * 16 + 8 + k];
            g10[mt] = sm[OFF_TRI + (n0 + 8) * 16 + k];
            g11[mt] = sm[OFF_TRI + (n0 + 8) * 16 + 8 + k];
        }

        float acc[2][8][4];
#pragma unroll
        for (int mt = 0; mt < 2; ++mt)
#pragma unroll
            for (int nt = 0; nt < 8; ++nt)
#pragma unroll
                for (int c = 0; c < 4; ++c) acc[mt][nt][c] = 0.f;

        const float* W1a = &sm[OFF_W1 + (k * 2 + 0) * E2];
        const float* W1b = &sm[OFF_W1 + (k * 2 + 1) * E2];
        const float* B1  = &sm[OFF_B1 + k * E2];

#pragma unroll
        for (int kt = 0; kt < 8; ++kt) {
            const int e0 = kt * 16 + 2 * q;
            float wa0 = W1a[e0], wa1 = W1a[e0+1], wa8 = W1a[e0+8], wa9 = W1a[e0+9];
            float wb0 = W1b[e0], wb1 = W1b[e0+1], wb8 = W1b[e0+8], wb9 = W1b[e0+9];
            float bb0 = B1[e0],  bb1 = B1[e0+1],  bb8 = B1[e0+8],  bb9 = B1[e0+9];

            unsigned afr[2][4];
#pragma unroll
            for (int mt = 0; mt < 2; ++mt) {
                float a0 = g00[mt], a1 = g01[mt], c0 = g10[mt], c1 = g11[mt];
                float t;
                t = fmaxf(a0*wa0 + a1*wb0 + bb0, 0.f); float u00 = t*t;
                t = fmaxf(a0*wa1 + a1*wb1 + bb1, 0.f); float u01 = t*t;
                t = fmaxf(a0*wa8 + a1*wb8 + bb8, 0.f); float u08 = t*t;
                t = fmaxf(a0*wa9 + a1*wb9 + bb9, 0.f); float u09 = t*t;
                t = fmaxf(c0*wa0 + c1*wb0 + bb0, 0.f); float u10 = t*t;
                t = fmaxf(c0*wa1 + c1*wb1 + bb1, 0.f); float u11 = t*t;
                t = fmaxf(c0*wa8 + c1*wb8 + bb8, 0.f); float u18 = t*t;
                t = fmaxf(c0*wa9 + c1*wb9 + bb9, 0.f); float u19 = t*t;
                afr[mt][0] = pk_bf16x2(u00, u01);
                afr[mt][1] = pk_bf16x2(u10, u11);
                afr[mt][2] = pk_bf16x2(u08, u09);
                afr[mt][3] = pk_bf16x2(u18, u19);
            }
            const uint2* Bf = &g_W2frag[((k * 8 + kt) * 8) * 32 + lane];
#pragma unroll
            for (int nt = 0; nt < 8; ++nt) {
                uint2 b = Bf[nt * 32];
                mma_bf16(acc[0][nt], afr[0], b.x, b.y);
                mma_bf16(acc[1][nt], afr[1], b.x, b.y);
            }
        }

        const float* B2 = &sm[OFF_B2 + k * 64];
        const float* CG = &sm[OFF_CG + k * 64];
        const float* CB = &sm[OFF_CB + k * 64];
#pragma unroll
        for (int mt = 0; mt < 2; ++mt) {
            float s0 = 0.f, s1 = 0.f;
#pragma unroll
            for (int nt = 0; nt < 8; ++nt) {
                float2 b2v = *(const float2*)&B2[nt * 8 + 2 * q];
                acc[mt][nt][0] += b2v.x; acc[mt][nt][1] += b2v.y;
                acc[mt][nt][2] += b2v.x; acc[mt][nt][3] += b2v.y;
                s0 += acc[mt][nt][0] + acc[mt][nt][1];
                s1 += acc[mt][nt][2] + acc[mt][nt][3];
            }
            s0 += __shfl_xor_sync(0xffffffffu, s0, 1);
            s0 += __shfl_xor_sync(0xffffffffu, s0, 2);
            s1 += __shfl_xor_sync(0xffffffffu, s1, 1);
            s1 += __shfl_xor_sync(0xffffffffu, s1, 2);
            float mu0 = s0 * (1.0f / 64.0f), mu1 = s1 * (1.0f / 64.0f);
            float v0 = 0.f, v1 = 0.f;
#pragma unroll
            for (int nt = 0; nt < 8; ++nt) {
                float d0 = acc[mt][nt][0] - mu0, d1 = acc[mt][nt][1] - mu0;
                float d2 = acc[mt][nt][2] - mu1, d3 = acc[mt][nt][3] - mu1;
                v0 += d0 * d0 + d1 * d1;
                v1 += d2 * d2 + d3 * d3;
            }
            v0 += __shfl_xor_sync(0xffffffffu, v0, 1);
            v0 += __shfl_xor_sync(0xffffffffu, v0, 2);
            v1 += __shfl_xor_sync(0xffffffffu, v1, 1);
            v1 += __shfl_xor_sync(0xffffffffu, v1, 2);
            float r0 = rsqrtf(v0 * (1.0f / 64.0f) + 1e-5f);
            float r1 = rsqrtf(v1 * (1.0f / 64.0f) + 1e-5f);

            // store directly in proj A-fragment layout (uint4 per lane per kstep)
            const long mtile = (base_tok >> 4) + mt;
#pragma unroll
            for (int nt2 = 0; nt2 < 4; ++nt2) {
                uint4 frag;
                {
                    int nt = 2 * nt2;
                    int col = nt * 8 + 2 * q;
                    float2 cgv = *(const float2*)&CG[col];
                    float2 cbv = *(const float2*)&CB[col];
                    frag.x = pk_bf16x2((acc[mt][nt][0] - mu0) * r0 * cgv.x + cbv.x,
                                       (acc[mt][nt][1] - mu0) * r0 * cgv.y + cbv.y);
                    frag.y = pk_bf16x2((acc[mt][nt][2] - mu1) * r1 * cgv.x + cbv.x,
                                       (acc[mt][nt][3] - mu1) * r1 * cgv.y + cbv.y);
                }
                {
                    int nt = 2 * nt2 + 1;
                    int col = nt * 8 + 2 * q;
                    float2 cgv = *(const float2*)&CG[col];
                    float2 cbv = *(const float2*)&CB[col];
                    frag.z = pk_bf16x2((acc[mt][nt][0] - mu0) * r0 * cgv.x + cbv.x,
                                       (acc[mt][nt][1] - mu0) * r0 * cgv.y + cbv.y);
                    frag.w = pk_bf16x2((acc[mt][nt][2] - mu1) * r1 * cgv.x + cbv.x,
                                       (acc[mt][nt][3] - mu1) * r1 * cgv.y + cbv.y);
                }
                int ks = k * 4 + nt2;
                g_Yfrag[((size_t)mtile * 32 + ks) * 32 + lane] = frag;
            }
        }
    }
}

// ================= K2: fragment-direct bf16 HMMA proj GEMM + gated residual =================
// CTA 128x128; 8 warps (2M x 4N), warp 64x32. Operands loaded as prebuilt HMMA
// fragments straight from global (L2-resident) — no smem tiles, no ldmatrix.
#define PSM_TOTAL 67584   // epilogue staging only: 128*132*4

__global__ void __launch_bounds__(256, 2)
proj_kernel(const float* __restrict__ bp, const float* __restrict__ x, float* __restrict__ out)
{
    extern __shared__ float smf[];
    const int tid = threadIdx.x, lane = tid & 31, wid = tid >> 5;
    const int wm = wid & 1, wn = wid >> 1;      // 2M x 4N
    const long m0 = (long)blockIdx.y * 128;
    const int n0 = blockIdx.x * 128;

    float acc[4][4][4];
#pragma unroll
    for (int mt = 0; mt < 4; ++mt)
#pragma unroll
        for (int nt = 0; nt < 4; ++nt)
#pragma unroll
            for (int c = 0; c < 4; ++c) acc[mt][nt][c] = 0.f;

    const uint4* Af[4];
#pragma unroll
    for (int mt = 0; mt < 4; ++mt)
        Af[mt] = g_Yfrag + ((size_t)((m0 >> 4) + wm * 4 + mt) * 32) * 32 + lane;
    const uint2* Bf[4];
#pragma unroll
    for (int nq = 0; nq < 4; ++nq)
        Bf[nq] = g_WpFrag + ((size_t)((n0 >> 3) + wn * 4 + nq) * 32) * 32 + lane;

    // register ping-pong: prefetch kstep+1 while issuing MMAs for kstep
    uint4 a0[4]; uint2 b0[4];
#pragma unroll
    for (int mt = 0; mt < 4; ++mt) a0[mt] = Af[mt][0];
#pragma unroll
    for (int nq = 0; nq < 4; ++nq) b0[nq] = Bf[nq][0];

    for (int ks = 0; ks < 32; ++ks) {
        uint4 a1[4]; uint2 b1[4];
        if (ks + 1 < 32) {
#pragma unroll
            for (int mt = 0; mt < 4; ++mt) a1[mt] = Af[mt][(ks + 1) * 32];
#pragma unroll
            for (int nq = 0; nq < 4; ++nq) b1[nq] = Bf[nq][(ks + 1) * 32];
        }
#pragma unroll
        for (int mt = 0; mt < 4; ++mt)
#pragma unroll
            for (int nq = 0; nq < 4; ++nq)
                mma_bf16(acc[mt][nq], (const unsigned*)&a0[mt], b0[nq].x, b0[nq].y);
        if (ks + 1 < 32) {
#pragma unroll
            for (int mt = 0; mt < 4; ++mt) a0[mt] = a1[mt];
#pragma unroll
            for (int nq = 0; nq < 4; ++nq) b0[nq] = b1[nq];
        }
    }

    // stage accumulators to smem [128][132]
#pragma unroll
    for (int mt = 0; mt < 4; ++mt) {
        int r0 = wm * 64 + mt * 16 + (lane >> 2);
#pragma unroll
        for (int nt = 0; nt < 4; ++nt) {
            int c = wn * 32 + nt * 8 + 2 * (lane & 3);
            *(float2*)&smf[r0 * 132 + c]       = make_float2(acc[mt][nt][0], acc[mt][nt][1]);
            *(float2*)&smf[(r0 + 8) * 132 + c] = make_float2(acc[mt][nt][2], acc[mt][nt][3]);
        }
    }
    __syncthreads();

    // coalesced gated-residual epilogue
    const int cc = lane * 4;
    float4 gs  = *(const float4*)&g_gatesig[n0 + cc];
    float4 bpv = *(const float4*)(bp + n0 + cc);
#pragma unroll
    for (int it = 0; it < 16; ++it) {
        int rr = it * 8 + wid;
        float4 v = *(float4*)&smf[rr * 132 + cc];
        const float* xr = x + (m0 + rr) * (long)Dd + n0 + cc;
        float4 xv = *(const float4*)xr;
        float4 o;
        o.x = xv.x + gs.x * (v.x + bpv.x);
        o.y = xv.y + gs.y * (v.y + bpv.y);
        o.z = xv.z + gs.z * (v.z + bpv.z);
        o.w = xv.w + gs.w * (v.w + bpv.w);
        *(float4*)(out + (m0 + rr) * (long)Dd + n0 + cc) = o;
    }
}

// ================= launch =================
extern "C" void kernel_launch(void* const* d_in, const int* in_sizes, int n_in,
                              void* d_out, int out_size) {
    const float* x       = (const float*)d_in[0];
    const float* anchors = (const float*)d_in[1];
    const float* ln_g    = (const float*)d_in[2];
    const float* ln_b    = (const float*)d_in[3];
    const float* W1      = (const float*)d_in[4];
    const float* b1      = (const float*)d_in[5];
    const float* W2      = (const float*)d_in[6];
    const float* b2      = (const float*)d_in[7];
    const float* cg      = (const float*)d_in[8];
    const float* cb      = (const float*)d_in[9];
    const float* Wp      = (const float*)d_in[10];
    const float* bp      = (const float*)d_in[11];
    const float* gate    = (const float*)d_in[12];
    float* out = (float*)d_out;

    const int Ntok = in_sizes[0] / Dd;   // 32768

    cudaFuncSetAttribute(token_kernel, cudaFuncAttributeMaxDynamicSharedMemorySize,
                         SM_FLOATS * sizeof(float));
    cudaFuncSetAttribute(proj_kernel, cudaFuncAttributeMaxDynamicSharedMemorySize, PSM_TOTAL);

    prep_kernel<<<Aa + 1 + 64 + Cc, 256>>>(anchors, gate, Wp, W2);
    prep2_kernel<<<4, 256>>>();
    token_kernel<<<Ntok / TB, 256, SM_FLOATS * sizeof(float)>>>(
        x, ln_g, ln_b, W1, b1, b2, cg, cb);
    proj_kernel<<<dim3(Dd / 128, Ntok / 128), 256, PSM_TOTAL>>>(bp, x, out);
}

// round 12
// speedup vs baseline: 1.1511x; 1.1511x over previous
#include <cuda_runtime.h>
#include <cuda_bf16.h>
#include <math.h>

// Problem constants (fixed shapes)
#define Dd 1024
#define Aa 16
#define Cc 8
#define DCc 64
#define CDd 512      // C*dc
#define E2 128       // 2*dc
#define TB 32        // tokens per CTA in token_kernel
#define NMAX 32768

// -------- device scratch (no allocations allowed) --------
__device__ __align__(16) float g_gatesig[Dd];                    // sigmoid(gate)
__device__ __align__(16) __nv_bfloat16 g_Yb[(size_t)NMAX * CDd]; // 32 MB: y_flat (bf16)
__device__ __align__(16) __nv_bfloat16 g_Wpb[CDd * Dd];          // Wp in bf16 [k][n]
__device__ __align__(16) uint2 g_W2frag[Cc * 8 * 8 * 32];        // W2 in HMMA B-fragment layout
__device__ __align__(16) uint2 g_AnFrag[64 * 2 * 32];            // anchors in HMMA B-fragment layout

__device__ __forceinline__ float wsum(float v) {
#pragma unroll
    for (int o = 16; o; o >>= 1) v += __shfl_xor_sync(0xffffffffu, v, o);
    return v;
}

// -------- tensor-core helpers --------
__device__ __forceinline__ void ldm_x4(unsigned* r, unsigned addr) {
    asm volatile("ldmatrix.sync.aligned.m8n8.x4.shared.b16 {%0,%1,%2,%3}, [%4];"
        : "=r"(r[0]), "=r"(r[1]), "=r"(r[2]), "=r"(r[3]) : "r"(addr));
}
__device__ __forceinline__ void ldm_x4_t(unsigned* r, unsigned addr) {
    asm volatile("ldmatrix.sync.aligned.m8n8.x4.trans.shared.b16 {%0,%1,%2,%3}, [%4];"
        : "=r"(r[0]), "=r"(r[1]), "=r"(r[2]), "=r"(r[3]) : "r"(addr));
}
__device__ __forceinline__ void mma_bf16(float* d, const unsigned* a, unsigned b0, unsigned b1) {
    asm volatile("mma.sync.aligned.m16n8k16.row.col.f32.bf16.bf16.f32 "
        "{%0,%1,%2,%3}, {%4,%5,%6,%7}, {%8,%9}, {%0,%1,%2,%3};"
        : "+f"(d[0]), "+f"(d[1]), "+f"(d[2]), "+f"(d[3])
        : "r"(a[0]), "r"(a[1]), "r"(a[2]), "r"(a[3]), "r"(b0), "r"(b1));
}
__device__ __forceinline__ void cpa16(unsigned saddr, const void* g) {
    asm volatile("cp.async.cg.shared.global [%0], [%1], 16;" :: "r"(saddr), "l"(g));
}
#define CP_COMMIT() asm volatile("cp.async.commit_group;")
#define CP_WAIT0()  asm volatile("cp.async.wait_group 0;")

__device__ __forceinline__ unsigned pk_bf16x2(float lo, float hi) {
    __nv_bfloat162 t = __floats2bfloat162_rn(lo, hi);
    return *reinterpret_cast<unsigned*>(&t);
}

// ================= K0: prep (Wp->bf16, gate, W2 fragments, anchor fragments) =================
__global__ void prep_kernel(const float* __restrict__ anchors, const float* __restrict__ gate,
                            const float* __restrict__ Wp, const float* __restrict__ W2) {
    int tid = threadIdx.x, lane = tid & 31, wid = tid >> 5;
    if (blockIdx.x < 64) {
        // Wp -> bf16 [k][n]
        int base = blockIdx.x * 8192;
#pragma unroll
        for (int j = 0; j < 8; ++j) {
            int pos = base + (tid + j * 256) * 4;
            float4 v = *(const float4*)(Wp + pos);
            __nv_bfloat162 lo = __floats2bfloat162_rn(v.x, v.y);
            __nv_bfloat162 hi = __floats2bfloat162_rn(v.z, v.w);
            *(__nv_bfloat162*)(g_Wpb + pos)     = lo;
            *(__nv_bfloat162*)(g_Wpb + pos + 2) = hi;
        }
    } else if (blockIdx.x == 64) {
        for (int i = tid; i < Dd; i += 256)
            g_gatesig[i] = 1.0f / (1.0f + expf(-gate[i]));
    } else if (blockIdx.x < 64 + 1 + Cc) {
        // W2 -> HMMA B-fragment layout, one block per comp
        int k = blockIdx.x - 65;
        const float* w = W2 + (long)k * E2 * DCc;   // [128][64]
        for (int idx = tid; idx < 2048; idx += 256) {
            int kt = idx >> 8;
            int rem = idx & 255;
            int nt = rem >> 5;
            int ln = rem & 31;
            int q = ln & 3, gg = ln >> 2;
            int N = nt * 8 + gg;
            int e0 = kt * 16 + 2 * q;
            uint2 val;
            val.x = pk_bf16x2(w[e0 * 64 + N],       w[(e0 + 1) * 64 + N]);
            val.y = pk_bf16x2(w[(e0 + 8) * 64 + N], w[(e0 + 9) * 64 + N]);
            g_W2frag[((k * 8 + kt) * 8 + nt) * 32 + ln] = val;
        }
    } else {
        // Anchor fragments with self-normalization (replaces prep2)
        __shared__ float ainv[Aa];
        // warp w handles anchors 2w, 2w+1
#pragma unroll
        for (int t = 0; t < 2; ++t) {
            int a = wid * 2 + t;
            float s = 0.f;
#pragma unroll
            for (int q = 0; q < 8; ++q) {
                float4 v = *(const float4*)(anchors + a * Dd + q * 128 + lane * 4);
                s += v.x * v.x + v.y * v.y + v.z * v.z + v.w * v.w;
            }
            s = wsum(s);
            if (lane == 0) ainv[a] = 1.0f / fmaxf(sqrtf(s), 1e-12f);
        }
        __syncthreads();
        for (int e = tid; e < 64 * 2 * 32; e += 256) {
            int ln = e & 31, nt = (e >> 5) & 1, kt = e >> 6;
            int q = ln & 3, gg = ln >> 2;
            int n = nt * 8 + gg;
            int k0 = kt * 16 + 2 * q;
            float inv = ainv[n];
            uint2 val;
            val.x = pk_bf16x2(anchors[n * Dd + k0] * inv,     anchors[n * Dd + k0 + 1] * inv);
            val.y = pk_bf16x2(anchors[n * Dd + k0 + 8] * inv, anchors[n * Dd + k0 + 9] * inv);
            g_AnFrag[(kt * 2 + nt) * 32 + ln] = val;
        }
    }
}

// ================= K1: LN/L2 -> bf16 H -> HMMA dots -> warp-per-comp HMMA MLP =================
#define OFF_H    0        // 16384 floats = 64 KB: H tile 32 x 1024 bf16 (row stride 2048 B, swizzled)
#define OFF_W1   16384
#define OFF_B1   18432
#define OFF_B2   19456
#define OFF_CG   19968
#define OFF_CB   20480
#define OFF_TRI  20992
#define OFF_LNG  21504
#define OFF_LNB  22528
#define OFF_PART 23552
#define SM_FLOATS 25600   // 102400 bytes

__global__ void __launch_bounds__(256, 2)
token_kernel(const float* __restrict__ x,
             const float* __restrict__ ln_g, const float* __restrict__ ln_b,
             const float* __restrict__ W1, const float* __restrict__ b1,
             const float* __restrict__ b2, const float* __restrict__ cg,
             const float* __restrict__ cb)
{
    extern __shared__ float sm[];
    const unsigned sbase = (unsigned)__cvta_generic_to_shared(sm);
    const int tid = threadIdx.x, lane = tid & 31, wid = tid >> 5;

    for (int t = tid; t < 512; t += 256)
        *(float4*)&sm[OFF_W1 + t * 4] = *(const float4*)&W1[t * 4];
    *(float4*)&sm[OFF_B1 + tid * 4] = *(const float4*)&b1[tid * 4];
    if (tid < 128) {
        *(float4*)&sm[OFF_B2 + tid * 4] = *(const float4*)&b2[tid * 4];
        *(float4*)&sm[OFF_CG + tid * 4] = *(const float4*)&cg[tid * 4];
        *(float4*)&sm[OFF_CB + tid * 4] = *(const float4*)&cb[tid * 4];
    }
    *(float4*)&sm[OFF_LNG + tid * 4] = *(const float4*)&ln_g[tid * 4];
    *(float4*)&sm[OFF_LNB + tid * 4] = *(const float4*)&ln_b[tid * 4];
    __syncthreads();

    const long base_tok = (long)blockIdx.x * TB;

    // ---------- Phase A: 2 tokens per warp per round; fused sum+sumsq ----------
    for (int r = 0; r < 2; ++r) {
        const int na = r * 16 + wid * 2;           // tokens na, na+1
        const float* xra = x + (base_tok + na) * (long)Dd;
        const float* xrb = xra + Dd;
        float va[32], vb[32];
#pragma unroll
        for (int q = 0; q < 8; ++q) {
            float4 ta = *(const float4*)(xra + q * 128 + lane * 4);
            float4 tb = *(const float4*)(xrb + q * 128 + lane * 4);
            va[q*4+0] = ta.x; va[q*4+1] = ta.y; va[q*4+2] = ta.z; va[q*4+3] = ta.w;
            vb[q*4+0] = tb.x; vb[q*4+1] = tb.y; vb[q*4+2] = tb.z; vb[q*4+3] = tb.w;
        }
        float sa = 0.f, qa = 0.f, sb = 0.f, qb = 0.f;
#pragma unroll
        for (int i = 0; i < 32; ++i) {
            sa += va[i]; qa = fmaf(va[i], va[i], qa);
            sb += vb[i]; qb = fmaf(vb[i], vb[i], qb);
        }
#pragma unroll
        for (int o = 16; o; o >>= 1) {
            sa += __shfl_xor_sync(0xffffffffu, sa, o);
            sb += __shfl_xor_sync(0xffffffffu, sb, o);
            qa += __shfl_xor_sync(0xffffffffu, qa, o);
            qb += __shfl_xor_sync(0xffffffffu, qb, o);
        }
        const float mua = sa * (1.0f / Dd), mub = sb * (1.0f / Dd);
        const float rsa = rsqrtf(fmaxf(qa * (1.0f / Dd) - mua * mua, 0.f) + 1e-5f);
        const float rsb = rsqrtf(fmaxf(qb * (1.0f / Dd) - mub * mub, 0.f) + 1e-5f);

        float n2a = 0.f, n2b = 0.f;
#pragma unroll
        for (int q = 0; q < 8; ++q) {
            float4 gv = *(const float4*)&sm[OFF_LNG + q * 128 + lane * 4];
            float4 bv = *(const float4*)&sm[OFF_LNB + q * 128 + lane * 4];
            float a0 = (va[q*4+0] - mua) * rsa * gv.x + bv.x;
            float a1 = (va[q*4+1] - mua) * rsa * gv.y + bv.y;
            float a2 = (va[q*4+2] - mua) * rsa * gv.z + bv.z;
            float a3 = (va[q*4+3] - mua) * rsa * gv.w + bv.w;
            float c0 = (vb[q*4+0] - mub) * rsb * gv.x + bv.x;
            float c1 = (vb[q*4+1] - mub) * rsb * gv.y + bv.y;
            float c2 = (vb[q*4+2] - mub) * rsb * gv.z + bv.z;
            float c3 = (vb[q*4+3] - mub) * rsb * gv.w + bv.w;
            va[q*4+0] = a0; va[q*4+1] = a1; va[q*4+2] = a2; va[q*4+3] = a3;
            vb[q*4+0] = c0; vb[q*4+1] = c1; vb[q*4+2] = c2; vb[q*4+3] = c3;
            n2a += a0*a0 + a1*a1 + a2*a2 + a3*a3;
            n2b += c0*c0 + c1*c1 + c2*c2 + c3*c3;
        }
#pragma unroll
        for (int o = 16; o; o >>= 1) {
            n2a += __shfl_xor_sync(0xffffffffu, n2a, o);
            n2b += __shfl_xor_sync(0xffffffffu, n2b, o);
        }
        const float inva = 1.0f / fmaxf(sqrtf(n2a), 1e-12f);
        const float invb = 1.0f / fmaxf(sqrtf(n2b), 1e-12f);

        char* hra = (char*)sm + na * 2048;
        char* hrb = hra + 2048;
        const unsigned swa = (unsigned)((na & 7) << 4);
        const unsigned swb = (unsigned)(((na + 1) & 7) << 4);
#pragma unroll
        for (int q = 0; q < 8; ++q) {
            unsigned off = (unsigned)(q * 256 + lane * 8);
            *(uint2*)(hra + (off ^ swa)) =
                make_uint2(pk_bf16x2(va[q*4+0]*inva, va[q*4+1]*inva),
                           pk_bf16x2(va[q*4+2]*inva, va[q*4+3]*inva));
            *(uint2*)(hrb + (off ^ swb)) =
                make_uint2(pk_bf16x2(vb[q*4+0]*invb, vb[q*4+1]*invb),
                           pk_bf16x2(vb[q*4+2]*invb, vb[q*4+3]*invb));
        }
    }
    __syncthreads();

    // ---------- Phase A2: tri = 1 - H @ Anchors^T via HMMA ----------
    {
        const int mt = wid & 1;
        const int kq = wid >> 1;
        const int al = lane & 15, ah = lane >> 4;
        const unsigned rowb = (unsigned)(mt * 16 + al);
        const unsigned rowoff = rowb * 2048;
        const unsigned swz = (rowb & 7) << 4;

        float acc[2][4];
#pragma unroll
        for (int nt = 0; nt < 2; ++nt)
#pragma unroll
            for (int c = 0; c < 4; ++c) acc[nt][c] = 0.f;

#pragma unroll
        for (int s = 0; s < 16; ++s) {
            const int kt = kq * 16 + s;
            unsigned afr[4];
            unsigned off = rowoff + (((unsigned)(kt * 32 + ah * 16)) ^ swz);
            ldm_x4(afr, sbase + off);
            uint2 b0 = g_AnFrag[(kt * 2 + 0) * 32 + lane];
            uint2 b1 = g_AnFrag[(kt * 2 + 1) * 32 + lane];
            mma_bf16(acc[0], afr, b0.x, b0.y);
            mma_bf16(acc[1], afr, b1.x, b1.y);
        }
        float* P = &sm[OFF_PART + kq * 512];
        const int r0 = mt * 16 + (lane >> 2);
        const int c0 = 2 * (lane & 3);
        P[r0 * 16 + c0]           = acc[0][0];
        P[r0 * 16 + c0 + 1]       = acc[0][1];
        P[(r0 + 8) * 16 + c0]     = acc[0][2];
        P[(r0 + 8) * 16 + c0 + 1] = acc[0][3];
        P[r0 * 16 + 8 + c0]           = acc[1][0];
        P[r0 * 16 + 8 + c0 + 1]       = acc[1][1];
        P[(r0 + 8) * 16 + 8 + c0]     = acc[1][2];
        P[(r0 + 8) * 16 + 8 + c0 + 1] = acc[1][3];
    }
    __syncthreads();
    for (int t = tid; t < 512; t += 256) {
        float d = sm[OFF_PART + t] + sm[OFF_PART + 512 + t]
                + sm[OFF_PART + 1024 + t] + sm[OFF_PART + 1536 + t];
        sm[OFF_TRI + t] = 1.0f - d;
    }
    __syncthreads();

    // ---------- Phase B: warp w = compartment w ----------
    {
        const int k = wid;
        const int q = lane & 3, rr = lane >> 2;

        float g00[2], g01[2], g10[2], g11[2];
#pragma unroll
        for (int mt = 0; mt < 2; ++mt) {
            int n0 = mt * 16 + rr;
            g00[mt] = sm[OFF_TRI + n0 * 16 + k];
            g01[mt] = sm[OFF_TRI + n0 * 16 + 8 + k];
            g10[mt] = sm[OFF_TRI + (n0 + 8) * 16 + k];
            g11[mt] = sm[OFF_TRI + (n0 + 8) * 16 + 8 + k];
        }

        float acc[2][8][4];
#pragma unroll
        for (int mt = 0; mt < 2; ++mt)
#pragma unroll
            for (int nt = 0; nt < 8; ++nt)
#pragma unroll
                for (int c = 0; c < 4; ++c) acc[mt][nt][c] = 0.f;

        const float* W1a = &sm[OFF_W1 + (k * 2 + 0) * E2];
        const float* W1b = &sm[OFF_W1 + (k * 2 + 1) * E2];
        const float* B1  = &sm[OFF_B1 + k * E2];

#pragma unroll
        for (int kt = 0; kt < 8; ++kt) {
            const int e0 = kt * 16 + 2 * q;
            float wa0 = W1a[e0], wa1 = W1a[e0+1], wa8 = W1a[e0+8], wa9 = W1a[e0+9];
            float wb0 = W1b[e0], wb1 = W1b[e0+1], wb8 = W1b[e0+8], wb9 = W1b[e0+9];
            float bb0 = B1[e0],  bb1 = B1[e0+1],  bb8 = B1[e0+8],  bb9 = B1[e0+9];

            unsigned afr[2][4];
#pragma unroll
            for (int mt = 0; mt < 2; ++mt) {
                float a0 = g00[mt], a1 = g01[mt], c0 = g10[mt], c1 = g11[mt];
                float t;
                t = fmaxf(a0*wa0 + a1*wb0 + bb0, 0.f); float u00 = t*t;
                t = fmaxf(a0*wa1 + a1*wb1 + bb1, 0.f); float u01 = t*t;
                t = fmaxf(a0*wa8 + a1*wb8 + bb8, 0.f); float u08 = t*t;
                t = fmaxf(a0*wa9 + a1*wb9 + bb9, 0.f); float u09 = t*t;
                t = fmaxf(c0*wa0 + c1*wb0 + bb0, 0.f); float u10 = t*t;
                t = fmaxf(c0*wa1 + c1*wb1 + bb1, 0.f); float u11 = t*t;
                t = fmaxf(c0*wa8 + c1*wb8 + bb8, 0.f); float u18 = t*t;
                t = fmaxf(c0*wa9 + c1*wb9 + bb9, 0.f); float u19 = t*t;
                afr[mt][0] = pk_bf16x2(u00, u01);
                afr[mt][1] = pk_bf16x2(u10, u11);
                afr[mt][2] = pk_bf16x2(u08, u09);
                afr[mt][3] = pk_bf16x2(u18, u19);
            }
            const uint2* Bf = &g_W2frag[((k * 8 + kt) * 8) * 32 + lane];
#pragma unroll
            for (int nt = 0; nt < 8; ++nt) {
                uint2 b = Bf[nt * 32];
                mma_bf16(acc[0][nt], afr[0], b.x, b.y);
                mma_bf16(acc[1][nt], afr[1], b.x, b.y);
            }
        }

        const float* B2 = &sm[OFF_B2 + k * 64];
        const float* CG = &sm[OFF_CG + k * 64];
        const float* CB = &sm[OFF_CB + k * 64];
#pragma unroll
        for (int mt = 0; mt < 2; ++mt) {
            float s0 = 0.f, s1 = 0.f;
#pragma unroll
            for (int nt = 0; nt < 8; ++nt) {
                float2 b2v = *(const float2*)&B2[nt * 8 + 2 * q];
                acc[mt][nt][0] += b2v.x; acc[mt][nt][1] += b2v.y;
                acc[mt][nt][2] += b2v.x; acc[mt][nt][3] += b2v.y;
                s0 += acc[mt][nt][0] + acc[mt][nt][1];
                s1 += acc[mt][nt][2] + acc[mt][nt][3];
            }
            s0 += __shfl_xor_sync(0xffffffffu, s0, 1);
            s0 += __shfl_xor_sync(0xffffffffu, s0, 2);
            s1 += __shfl_xor_sync(0xffffffffu, s1, 1);
            s1 += __shfl_xor_sync(0xffffffffu, s1, 2);
            float mu0 = s0 * (1.0f / 64.0f), mu1 = s1 * (1.0f / 64.0f);
            float v0 = 0.f, v1 = 0.f;
#pragma unroll
            for (int nt = 0; nt < 8; ++nt) {
                float d0 = acc[mt][nt][0] - mu0, d1 = acc[mt][nt][1] - mu0;
                float d2 = acc[mt][nt][2] - mu1, d3 = acc[mt][nt][3] - mu1;
                v0 += d0 * d0 + d1 * d1;
                v1 += d2 * d2 + d3 * d3;
            }
            v0 += __shfl_xor_sync(0xffffffffu, v0, 1);
            v0 += __shfl_xor_sync(0xffffffffu, v0, 2);
            v1 += __shfl_xor_sync(0xffffffffu, v1, 1);
            v1 += __shfl_xor_sync(0xffffffffu, v1, 2);
            float r0 = rsqrtf(v0 * (1.0f / 64.0f) + 1e-5f);
            float r1 = rsqrtf(v1 * (1.0f / 64.0f) + 1e-5f);

            long n0 = base_tok + mt * 16 + rr;
            __nv_bfloat16* y0 = g_Yb + n0 * (long)CDd + k * 64;
            __nv_bfloat16* y1 = y0 + 8 * (long)CDd;
#pragma unroll
            for (int nt = 0; nt < 8; ++nt) {
                int col = nt * 8 + 2 * q;
                float2 cgv = *(const float2*)&CG[col];
                float2 cbv = *(const float2*)&CB[col];
                unsigned p0 = pk_bf16x2((acc[mt][nt][0] - mu0) * r0 * cgv.x + cbv.x,
                                        (acc[mt][nt][1] - mu0) * r0 * cgv.y + cbv.y);
                unsigned p1 = pk_bf16x2((acc[mt][nt][2] - mu1) * r1 * cgv.x + cbv.x,
                                        (acc[mt][nt][3] - mu1) * r1 * cgv.y + cbv.y);
                *(unsigned*)(y0 + col) = p0;
                *(unsigned*)(y1 + col) = p1;
            }
        }
    }
}

// ================= K2: bf16 HMMA proj GEMM, 256x128 CTA tile, 512 threads =================
// 16 warps (4M x 4N), warp 64x32; K-chunk 64, double-buffered cp.async.
// smem: A 2x32KB + B 2x16KB = 96KB, 1 CTA/SM but same 16 warps/SM as 2x(128x128).
#define PSM_TOTAL 98304

__global__ void __launch_bounds__(512, 1)
proj_kernel(const float* __restrict__ bp, const float* __restrict__ x, float* __restrict__ out)
{
    extern __shared__ char psm[];
    const unsigned sbase = (unsigned)__cvta_generic_to_shared(psm);
    const unsigned sA = sbase;            // 2 x 32 KB (256 rows x 128 B)
    const unsigned sB = sbase + 65536;    // 2 x 16 KB (64 rows x 256 B)
    const int tid = threadIdx.x, lane = tid & 31, wid = tid >> 5;
    const int wm = wid & 3, wn = wid >> 2;      // 4M x 4N
    const long m0 = (long)blockIdx.y * 256;
    const int n0 = blockIdx.x * 128;

    float acc[4][4][4];
#pragma unroll
    for (int mt = 0; mt < 4; ++mt)
#pragma unroll
        for (int nt = 0; nt < 4; ++nt)
#pragma unroll
            for (int c = 0; c < 4; ++c) acc[mt][nt][c] = 0.f;

    auto loadTile = [&](int kc, int buf) {
        unsigned Ab = sA + buf * 32768;
        unsigned Bb = sB + buf * 16384;
        // A: 2048 16B-chunks, 4 per thread
#pragma unroll
        for (int i = 0; i < 4; ++i) {
            int chunk = tid + i * 512;
            int r = chunk >> 3, c16 = chunk & 7;
            unsigned off = (unsigned)(r * 128 + c16 * 16);
            cpa16(Ab + (off ^ ((r & 7) << 4)),
                  g_Yb + (m0 + r) * (long)CDd + kc * 64 + c16 * 8);
        }
        // B: 1024 16B-chunks, 2 per thread
#pragma unroll
        for (int i = 0; i < 2; ++i) {
            int chunk = tid + i * 512;
            int r = chunk >> 4, c16 = chunk & 15;
            unsigned off = (unsigned)(r * 256 + c16 * 16);
            cpa16(Bb + (off ^ ((r & 7) << 4)),
                  g_Wpb + (long)(kc * 64 + r) * Dd + n0 + c16 * 8);
        }
    };

    loadTile(0, 0);
    CP_COMMIT();

    const unsigned sw = (unsigned)((lane & 7) << 4);
    const int al = lane & 15, ah = lane >> 4;

    for (int kc = 0; kc < 8; ++kc) {
        CP_WAIT0();
        __syncthreads();
        if (kc + 1 < 8) { loadTile(kc + 1, (kc + 1) & 1); CP_COMMIT(); }

        unsigned Ab = sA + (kc & 1) * 32768;
        unsigned Bb = sB + (kc & 1) * 16384;
#pragma unroll
        for (int ks = 0; ks < 4; ++ks) {
            unsigned afr[4][4];
#pragma unroll
            for (int mt = 0; mt < 4; ++mt) {
                unsigned row = wm * 64 + mt * 16 + al;
                unsigned off = row * 128 + ks * 32 + ah * 16;
                ldm_x4(afr[mt], Ab + (off ^ sw));
            }
            unsigned bfr[2][4];
#pragma unroll
            for (int nq = 0; nq < 2; ++nq) {
                unsigned row = ks * 16 + al;
                unsigned off = row * 256 + (wn * 32 + nq * 16 + ah * 8) * 2;
                ldm_x4_t(bfr[nq], Bb + (off ^ sw));
            }
#pragma unroll
            for (int mt = 0; mt < 4; ++mt)
#pragma unroll
                for (int nq = 0; nq < 2; ++nq) {
                    mma_bf16(acc[mt][2 * nq],     afr[mt], bfr[nq][0], bfr[nq][1]);
                    mma_bf16(acc[mt][2 * nq + 1], afr[mt], bfr[nq][2], bfr[nq][3]);
                }
        }
        __syncthreads();
    }

    // direct gated-residual epilogue (4-lane clusters = aligned 32B sectors)
#pragma unroll
    for (int mt = 0; mt < 4; ++mt) {
        long row = m0 + wm * 64 + mt * 16 + (lane >> 2);
#pragma unroll
        for (int nt = 0; nt < 4; ++nt) {
            int col = n0 + wn * 32 + nt * 8 + 2 * (lane & 3);
            float2 gs  = *(const float2*)&g_gatesig[col];
            float2 bpv = *(const float2*)(bp + col);
            float2 xv0 = *(const float2*)(x + row * Dd + col);
            float2 xv1 = *(const float2*)(x + (row + 8) * Dd + col);
            float2 o0, o1;
            o0.x = xv0.x + gs.x * (acc[mt][nt][0] + bpv.x);
            o0.y = xv0.y + gs.y * (acc[mt][nt][1] + bpv.y);
            o1.x = xv1.x + gs.x * (acc[mt][nt][2] + bpv.x);
            o1.y = xv1.y + gs.y * (acc[mt][nt][3] + bpv.y);
            *(float2*)(out + row * Dd + col) = o0;
            *(float2*)(out + (row + 8) * Dd + col) = o1;
        }
    }
}

// ================= launch =================
extern "C" void kernel_launch(void* const* d_in, const int* in_sizes, int n_in,
                              void* d_out, int out_size) {
    const float* x       = (const float*)d_in[0];
    const float* anchors = (const float*)d_in[1];
    const float* ln_g    = (const float*)d_in[2];
    const float* ln_b    = (const float*)d_in[3];
    const float* W1      = (const float*)d_in[4];
    const float* b1      = (const float*)d_in[5];
    const float* W2      = (const float*)d_in[6];
    const float* b2      = (const float*)d_in[7];
    const float* cg      = (const float*)d_in[8];
    const float* cb      = (const float*)d_in[9];
    const float* Wp      = (const float*)d_in[10];
    const float* bp      = (const float*)d_in[11];
    const float* gate    = (const float*)d_in[12];
    float* out = (float*)d_out;

    const int Ntok = in_sizes[0] / Dd;   // 32768

    cudaFuncSetAttribute(token_kernel, cudaFuncAttributeMaxDynamicSharedMemorySize,
                         SM_FLOATS * sizeof(float));
    cudaFuncSetAttribute(proj_kernel, cudaFuncAttributeMaxDynamicSharedMemorySize, PSM_TOTAL);

    prep_kernel<<<64 + 1 + Cc + 1, 256>>>(anchors, gate, Wp, W2);
    token_kernel<<<Ntok / TB, 256, SM_FLOATS * sizeof(float)>>>(
        x, ln_g, ln_b, W1, b1, b2, cg, cb);
    proj_kernel<<<dim3(Dd / 128, Ntok / 256), 512, PSM_TOTAL>>>(bp, x, out);
}

// round 13
// speedup vs baseline: 1.3363x; 1.1609x over previous
#include <cuda_runtime.h>
#include <cuda_bf16.h>
#include <math.h>

// Problem constants (fixed shapes)
#define Dd 1024
#define Aa 16
#define Cc 8
#define DCc 64
#define CDd 512      // C*dc
#define E2 128       // 2*dc
#define TB 32        // tokens per CTA in token_kernel
#define NMAX 32768

// -------- device scratch (no allocations allowed) --------
__device__ __align__(16) float g_gatesig[Dd];                    // sigmoid(gate)
__device__ __align__(16) __nv_bfloat16 g_Yb[(size_t)NMAX * CDd]; // 32 MB: y_flat (bf16)
__device__ __align__(16) __nv_bfloat16 g_Wpb[CDd * Dd];          // Wp in bf16 [k][n]
__device__ __align__(16) uint2 g_W2frag[Cc * 8 * 8 * 32];        // W2 in HMMA B-fragment layout
__device__ __align__(16) uint2 g_AnFrag[64 * 2 * 32];            // anchors in HMMA B-fragment layout

__device__ __forceinline__ float wsum(float v) {
#pragma unroll
    for (int o = 16; o; o >>= 1) v += __shfl_xor_sync(0xffffffffu, v, o);
    return v;
}

// -------- tensor-core helpers --------
__device__ __forceinline__ void ldm_x4(unsigned* r, unsigned addr) {
    asm volatile("ldmatrix.sync.aligned.m8n8.x4.shared.b16 {%0,%1,%2,%3}, [%4];"
        : "=r"(r[0]), "=r"(r[1]), "=r"(r[2]), "=r"(r[3]) : "r"(addr));
}
__device__ __forceinline__ void ldm_x4_t(unsigned* r, unsigned addr) {
    asm volatile("ldmatrix.sync.aligned.m8n8.x4.trans.shared.b16 {%0,%1,%2,%3}, [%4];"
        : "=r"(r[0]), "=r"(r[1]), "=r"(r[2]), "=r"(r[3]) : "r"(addr));
}
__device__ __forceinline__ void mma_bf16(float* d, const unsigned* a, unsigned b0, unsigned b1) {
    asm volatile("mma.sync.aligned.m16n8k16.row.col.f32.bf16.bf16.f32 "
        "{%0,%1,%2,%3}, {%4,%5,%6,%7}, {%8,%9}, {%0,%1,%2,%3};"
        : "+f"(d[0]), "+f"(d[1]), "+f"(d[2]), "+f"(d[3])
        : "r"(a[0]), "r"(a[1]), "r"(a[2]), "r"(a[3]), "r"(b0), "r"(b1));
}
__device__ __forceinline__ void cpa16(unsigned saddr, const void* g) {
    asm volatile("cp.async.cg.shared.global [%0], [%1], 16;" :: "r"(saddr), "l"(g));
}
#define CP_COMMIT() asm volatile("cp.async.commit_group;")
#define CP_WAIT0()  asm volatile("cp.async.wait_group 0;")

__device__ __forceinline__ unsigned pk_bf16x2(float lo, float hi) {
    __nv_bfloat162 t = __floats2bfloat162_rn(lo, hi);
    return *reinterpret_cast<unsigned*>(&t);
}

// ================= K0: prep (Wp->bf16, gate, W2 fragments, anchor fragments) =================
__global__ void prep_kernel(const float* __restrict__ anchors, const float* __restrict__ gate,
                            const float* __restrict__ Wp, const float* __restrict__ W2) {
    int tid = threadIdx.x, lane = tid & 31, wid = tid >> 5;
    if (blockIdx.x < 64) {
        // Wp -> bf16 [k][n]
        int base = blockIdx.x * 8192;
#pragma unroll
        for (int j = 0; j < 8; ++j) {
            int pos = base + (tid + j * 256) * 4;
            float4 v = *(const float4*)(Wp + pos);
            __nv_bfloat162 lo = __floats2bfloat162_rn(v.x, v.y);
            __nv_bfloat162 hi = __floats2bfloat162_rn(v.z, v.w);
            *(__nv_bfloat162*)(g_Wpb + pos)     = lo;
            *(__nv_bfloat162*)(g_Wpb + pos + 2) = hi;
        }
    } else if (blockIdx.x == 64) {
        for (int i = tid; i < Dd; i += 256)
            g_gatesig[i] = 1.0f / (1.0f + expf(-gate[i]));
    } else if (blockIdx.x < 64 + 1 + Cc) {
        // W2 -> HMMA B-fragment layout, one block per comp
        int k = blockIdx.x - 65;
        const float* w = W2 + (long)k * E2 * DCc;   // [128][64]
        for (int idx = tid; idx < 2048; idx += 256) {
            int kt = idx >> 8;
            int rem = idx & 255;
            int nt = rem >> 5;
            int ln = rem & 31;
            int q = ln & 3, gg = ln >> 2;
            int N = nt * 8 + gg;
            int e0 = kt * 16 + 2 * q;
            uint2 val;
            val.x = pk_bf16x2(w[e0 * 64 + N],       w[(e0 + 1) * 64 + N]);
            val.y = pk_bf16x2(w[(e0 + 8) * 64 + N], w[(e0 + 9) * 64 + N]);
            g_W2frag[((k * 8 + kt) * 8 + nt) * 32 + ln] = val;
        }
    } else {
        // Anchor fragments with self-normalization (merged prep2)
        __shared__ float ainv[Aa];
#pragma unroll
        for (int t = 0; t < 2; ++t) {
            int a = wid * 2 + t;
            float s = 0.f;
#pragma unroll
            for (int q = 0; q < 8; ++q) {
                float4 v = *(const float4*)(anchors + a * Dd + q * 128 + lane * 4);
                s += v.x * v.x + v.y * v.y + v.z * v.z + v.w * v.w;
            }
            s = wsum(s);
            if (lane == 0) ainv[a] = 1.0f / fmaxf(sqrtf(s), 1e-12f);
        }
        __syncthreads();
        for (int e = tid; e < 64 * 2 * 32; e += 256) {
            int ln = e & 31, nt = (e >> 5) & 1, kt = e >> 6;
            int q = ln & 3, gg = ln >> 2;
            int n = nt * 8 + gg;
            int k0 = kt * 16 + 2 * q;
            float inv = ainv[n];
            uint2 val;
            val.x = pk_bf16x2(anchors[n * Dd + k0] * inv,     anchors[n * Dd + k0 + 1] * inv);
            val.y = pk_bf16x2(anchors[n * Dd + k0 + 8] * inv, anchors[n * Dd + k0 + 9] * inv);
            g_AnFrag[(kt * 2 + nt) * 32 + ln] = val;
        }
    }
}

// ================= K1: LN/L2 -> bf16 H -> HMMA dots -> warp-per-comp HMMA MLP =================
#define OFF_H    0        // 16384 floats = 64 KB: H tile 32 x 1024 bf16 (row stride 2048 B, swizzled)
#define OFF_W1   16384
#define OFF_B1   18432
#define OFF_B2   19456
#define OFF_CG   19968
#define OFF_CB   20480
#define OFF_TRI  20992
#define OFF_LNG  21504
#define OFF_LNB  22528
#define OFF_PART 23552
#define SM_FLOATS 25600   // 102400 bytes

__global__ void __launch_bounds__(256, 2)
token_kernel(const float* __restrict__ x,
             const float* __restrict__ ln_g, const float* __restrict__ ln_b,
             const float* __restrict__ W1, const float* __restrict__ b1,
             const float* __restrict__ b2, const float* __restrict__ cg,
             const float* __restrict__ cb)
{
    extern __shared__ float sm[];
    const unsigned sbase = (unsigned)__cvta_generic_to_shared(sm);
    const int tid = threadIdx.x, lane = tid & 31, wid = tid >> 5;

    for (int t = tid; t < 512; t += 256)
        *(float4*)&sm[OFF_W1 + t * 4] = *(const float4*)&W1[t * 4];
    *(float4*)&sm[OFF_B1 + tid * 4] = *(const float4*)&b1[tid * 4];
    if (tid < 128) {
        *(float4*)&sm[OFF_B2 + tid * 4] = *(const float4*)&b2[tid * 4];
        *(float4*)&sm[OFF_CG + tid * 4] = *(const float4*)&cg[tid * 4];
        *(float4*)&sm[OFF_CB + tid * 4] = *(const float4*)&cb[tid * 4];
    }
    *(float4*)&sm[OFF_LNG + tid * 4] = *(const float4*)&ln_g[tid * 4];
    *(float4*)&sm[OFF_LNB + tid * 4] = *(const float4*)&ln_b[tid * 4];
    __syncthreads();

    const long base_tok = (long)blockIdx.x * TB;

    // ---------- Phase A: 2 tokens per warp per round; fused sum+sumsq ----------
    for (int r = 0; r < 2; ++r) {
        const int na = r * 16 + wid * 2;           // tokens na, na+1
        const float* xra = x + (base_tok + na) * (long)Dd;
        const float* xrb = xra + Dd;
        float va[32], vb[32];
#pragma unroll
        for (int q = 0; q < 8; ++q) {
            float4 ta = *(const float4*)(xra + q * 128 + lane * 4);
            float4 tb = *(const float4*)(xrb + q * 128 + lane * 4);
            va[q*4+0] = ta.x; va[q*4+1] = ta.y; va[q*4+2] = ta.z; va[q*4+3] = ta.w;
            vb[q*4+0] = tb.x; vb[q*4+1] = tb.y; vb[q*4+2] = tb.z; vb[q*4+3] = tb.w;
        }
        float sa = 0.f, qa = 0.f, sb = 0.f, qb = 0.f;
#pragma unroll
        for (int i = 0; i < 32; ++i) {
            sa += va[i]; qa = fmaf(va[i], va[i], qa);
            sb += vb[i]; qb = fmaf(vb[i], vb[i], qb);
        }
#pragma unroll
        for (int o = 16; o; o >>= 1) {
            sa += __shfl_xor_sync(0xffffffffu, sa, o);
            sb += __shfl_xor_sync(0xffffffffu, sb, o);
            qa += __shfl_xor_sync(0xffffffffu, qa, o);
            qb += __shfl_xor_sync(0xffffffffu, qb, o);
        }
        const float mua = sa * (1.0f / Dd), mub = sb * (1.0f / Dd);
        const float rsa = rsqrtf(fmaxf(qa * (1.0f / Dd) - mua * mua, 0.f) + 1e-5f);
        const float rsb = rsqrtf(fmaxf(qb * (1.0f / Dd) - mub * mub, 0.f) + 1e-5f);

        float n2a = 0.f, n2b = 0.f;
#pragma unroll
        for (int q = 0; q < 8; ++q) {
            float4 gv = *(const float4*)&sm[OFF_LNG + q * 128 + lane * 4];
            float4 bv = *(const float4*)&sm[OFF_LNB + q * 128 + lane * 4];
            float a0 = (va[q*4+0] - mua) * rsa * gv.x + bv.x;
            float a1 = (va[q*4+1] - mua) * rsa * gv.y + bv.y;
            float a2 = (va[q*4+2] - mua) * rsa * gv.z + bv.z;
            float a3 = (va[q*4+3] - mua) * rsa * gv.w + bv.w;
            float c0 = (vb[q*4+0] - mub) * rsb * gv.x + bv.x;
            float c1 = (vb[q*4+1] - mub) * rsb * gv.y + bv.y;
            float c2 = (vb[q*4+2] - mub) * rsb * gv.z + bv.z;
            float c3 = (vb[q*4+3] - mub) * rsb * gv.w + bv.w;
            va[q*4+0] = a0; va[q*4+1] = a1; va[q*4+2] = a2; va[q*4+3] = a3;
            vb[q*4+0] = c0; vb[q*4+1] = c1; vb[q*4+2] = c2; vb[q*4+3] = c3;
            n2a += a0*a0 + a1*a1 + a2*a2 + a3*a3;
            n2b += c0*c0 + c1*c1 + c2*c2 + c3*c3;
        }
#pragma unroll
        for (int o = 16; o; o >>= 1) {
            n2a += __shfl_xor_sync(0xffffffffu, n2a, o);
            n2b += __shfl_xor_sync(0xffffffffu, n2b, o);
        }
        const float inva = 1.0f / fmaxf(sqrtf(n2a), 1e-12f);
        const float invb = 1.0f / fmaxf(sqrtf(n2b), 1e-12f);

        char* hra = (char*)sm + na * 2048;
        char* hrb = hra + 2048;
        const unsigned swa = (unsigned)((na & 7) << 4);
        const unsigned swb = (unsigned)(((na + 1) & 7) << 4);
#pragma unroll
        for (int q = 0; q < 8; ++q) {
            unsigned off = (unsigned)(q * 256 + lane * 8);
            *(uint2*)(hra + (off ^ swa)) =
                make_uint2(pk_bf16x2(va[q*4+0]*inva, va[q*4+1]*inva),
                           pk_bf16x2(va[q*4+2]*inva, va[q*4+3]*inva));
            *(uint2*)(hrb + (off ^ swb)) =
                make_uint2(pk_bf16x2(vb[q*4+0]*invb, vb[q*4+1]*invb),
                           pk_bf16x2(vb[q*4+2]*invb, vb[q*4+3]*invb));
        }
    }
    __syncthreads();

    // ---------- Phase A2: tri = 1 - H @ Anchors^T via HMMA ----------
    {
        const int mt = wid & 1;
        const int kq = wid >> 1;
        const int al = lane & 15, ah = lane >> 4;
        const unsigned rowb = (unsigned)(mt * 16 + al);
        const unsigned rowoff = rowb * 2048;
        const unsigned swz = (rowb & 7) << 4;

        float acc[2][4];
#pragma unroll
        for (int nt = 0; nt < 2; ++nt)
#pragma unroll
            for (int c = 0; c < 4; ++c) acc[nt][c] = 0.f;

#pragma unroll
        for (int s = 0; s < 16; ++s) {
            const int kt = kq * 16 + s;
            unsigned afr[4];
            unsigned off = rowoff + (((unsigned)(kt * 32 + ah * 16)) ^ swz);
            ldm_x4(afr, sbase + off);
            uint2 b0 = g_AnFrag[(kt * 2 + 0) * 32 + lane];
            uint2 b1 = g_AnFrag[(kt * 2 + 1) * 32 + lane];
            mma_bf16(acc[0], afr, b0.x, b0.y);
            mma_bf16(acc[1], afr, b1.x, b1.y);
        }
        float* P = &sm[OFF_PART + kq * 512];
        const int r0 = mt * 16 + (lane >> 2);
        const int c0 = 2 * (lane & 3);
        P[r0 * 16 + c0]           = acc[0][0];
        P[r0 * 16 + c0 + 1]       = acc[0][1];
        P[(r0 + 8) * 16 + c0]     = acc[0][2];
        P[(r0 + 8) * 16 + c0 + 1] = acc[0][3];
        P[r0 * 16 + 8 + c0]           = acc[1][0];
        P[r0 * 16 + 8 + c0 + 1]       = acc[1][1];
        P[(r0 + 8) * 16 + 8 + c0]     = acc[1][2];
        P[(r0 + 8) * 16 + 8 + c0 + 1] = acc[1][3];
    }
    __syncthreads();
    for (int t = tid; t < 512; t += 256) {
        float d = sm[OFF_PART + t] + sm[OFF_PART + 512 + t]
                + sm[OFF_PART + 1024 + t] + sm[OFF_PART + 1536 + t];
        sm[OFF_TRI + t] = 1.0f - d;
    }
    __syncthreads();

    // ---------- Phase B: warp w = compartment w ----------
    {
        const int k = wid;
        const int q = lane & 3, rr = lane >> 2;

        float g00[2], g01[2], g10[2], g11[2];
#pragma unroll
        for (int mt = 0; mt < 2; ++mt) {
            int n0 = mt * 16 + rr;
            g00[mt] = sm[OFF_TRI + n0 * 16 + k];
            g01[mt] = sm[OFF_TRI + n0 * 16 + 8 + k];
            g10[mt] = sm[OFF_TRI + (n0 + 8) * 16 + k];
            g11[mt] = sm[OFF_TRI + (n0 + 8) * 16 + 8 + k];
        }

        float acc[2][8][4];
#pragma unroll
        for (int mt = 0; mt < 2; ++mt)
#pragma unroll
            for (int nt = 0; nt < 8; ++nt)
#pragma unroll
                for (int c = 0; c < 4; ++c) acc[mt][nt][c] = 0.f;

        const float* W1a = &sm[OFF_W1 + (k * 2 + 0) * E2];
        const float* W1b = &sm[OFF_W1 + (k * 2 + 1) * E2];
        const float* B1  = &sm[OFF_B1 + k * E2];

#pragma unroll
        for (int kt = 0; kt < 8; ++kt) {
            const int e0 = kt * 16 + 2 * q;
            float wa0 = W1a[e0], wa1 = W1a[e0+1], wa8 = W1a[e0+8], wa9 = W1a[e0+9];
            float wb0 = W1b[e0], wb1 = W1b[e0+1], wb8 = W1b[e0+8], wb9 = W1b[e0+9];
            float bb0 = B1[e0],  bb1 = B1[e0+1],  bb8 = B1[e0+8],  bb9 = B1[e0+9];

            unsigned afr[2][4];
#pragma unroll
            for (int mt = 0; mt < 2; ++mt) {
                float a0 = g00[mt], a1 = g01[mt], c0 = g10[mt], c1 = g11[mt];
                float t;
                t = fmaxf(a0*wa0 + a1*wb0 + bb0, 0.f); float u00 = t*t;
                t = fmaxf(a0*wa1 + a1*wb1 + bb1, 0.f); float u01 = t*t;
                t = fmaxf(a0*wa8 + a1*wb8 + bb8, 0.f); float u08 = t*t;
                t = fmaxf(a0*wa9 + a1*wb9 + bb9, 0.f); float u09 = t*t;
                t = fmaxf(c0*wa0 + c1*wb0 + bb0, 0.f); float u10 = t*t;
                t = fmaxf(c0*wa1 + c1*wb1 + bb1, 0.f); float u11 = t*t;
                t = fmaxf(c0*wa8 + c1*wb8 + bb8, 0.f); float u18 = t*t;
                t = fmaxf(c0*wa9 + c1*wb9 + bb9, 0.f); float u19 = t*t;
                afr[mt][0] = pk_bf16x2(u00, u01);
                afr[mt][1] = pk_bf16x2(u10, u11);
                afr[mt][2] = pk_bf16x2(u08, u09);
                afr[mt][3] = pk_bf16x2(u18, u19);
            }
            const uint2* Bf = &g_W2frag[((k * 8 + kt) * 8) * 32 + lane];
#pragma unroll
            for (int nt = 0; nt < 8; ++nt) {
                uint2 b = Bf[nt * 32];
                mma_bf16(acc[0][nt], afr[0], b.x, b.y);
                mma_bf16(acc[1][nt], afr[1], b.x, b.y);
            }
        }

        const float* B2 = &sm[OFF_B2 + k * 64];
        const float* CG = &sm[OFF_CG + k * 64];
        const float* CB = &sm[OFF_CB + k * 64];
#pragma unroll
        for (int mt = 0; mt < 2; ++mt) {
            float s0 = 0.f, s1 = 0.f;
#pragma unroll
            for (int nt = 0; nt < 8; ++nt) {
                float2 b2v = *(const float2*)&B2[nt * 8 + 2 * q];
                acc[mt][nt][0] += b2v.x; acc[mt][nt][1] += b2v.y;
                acc[mt][nt][2] += b2v.x; acc[mt][nt][3] += b2v.y;
                s0 += acc[mt][nt][0] + acc[mt][nt][1];
                s1 += acc[mt][nt][2] + acc[mt][nt][3];
            }
            s0 += __shfl_xor_sync(0xffffffffu, s0, 1);
            s0 += __shfl_xor_sync(0xffffffffu, s0, 2);
            s1 += __shfl_xor_sync(0xffffffffu, s1, 1);
            s1 += __shfl_xor_sync(0xffffffffu, s1, 2);
            float mu0 = s0 * (1.0f / 64.0f), mu1 = s1 * (1.0f / 64.0f);
            float v0 = 0.f, v1 = 0.f;
#pragma unroll
            for (int nt = 0; nt < 8; ++nt) {
                float d0 = acc[mt][nt][0] - mu0, d1 = acc[mt][nt][1] - mu0;
                float d2 = acc[mt][nt][2] - mu1, d3 = acc[mt][nt][3] - mu1;
                v0 += d0 * d0 + d1 * d1;
                v1 += d2 * d2 + d3 * d3;
            }
            v0 += __shfl_xor_sync(0xffffffffu, v0, 1);
            v0 += __shfl_xor_sync(0xffffffffu, v0, 2);
            v1 += __shfl_xor_sync(0xffffffffu, v1, 1);
            v1 += __shfl_xor_sync(0xffffffffu, v1, 2);
            float r0 = rsqrtf(v0 * (1.0f / 64.0f) + 1e-5f);
            float r1 = rsqrtf(v1 * (1.0f / 64.0f) + 1e-5f);

            long n0 = base_tok + mt * 16 + rr;
            __nv_bfloat16* y0 = g_Yb + n0 * (long)CDd + k * 64;
            __nv_bfloat16* y1 = y0 + 8 * (long)CDd;
#pragma unroll
            for (int nt = 0; nt < 8; ++nt) {
                int col = nt * 8 + 2 * q;
                float2 cgv = *(const float2*)&CG[col];
                float2 cbv = *(const float2*)&CB[col];
                unsigned p0 = pk_bf16x2((acc[mt][nt][0] - mu0) * r0 * cgv.x + cbv.x,
                                        (acc[mt][nt][1] - mu0) * r0 * cgv.y + cbv.y);
                unsigned p1 = pk_bf16x2((acc[mt][nt][2] - mu1) * r1 * cgv.x + cbv.x,
                                        (acc[mt][nt][3] - mu1) * r1 * cgv.y + cbv.y);
                *(unsigned*)(y0 + col) = p0;
                *(unsigned*)(y1 + col) = p1;
            }
        }
    }
}

// ================= K2: bf16 HMMA projection GEMM + gated residual (R6/R8 proven config) =================
// CTA 128x128, K-chunk 64, double-buffered cp.async, 8 warps (2M x 4N), warp 64x32.
// 64 KB smem -> 2 CTAs/SM (the empirically load-bearing configuration).
#define PSM_TOTAL 68608

__global__ void __launch_bounds__(256)
proj_kernel(const float* __restrict__ bp, const float* __restrict__ x, float* __restrict__ out)
{
    extern __shared__ char psm[];
    const unsigned sbase = (unsigned)__cvta_generic_to_shared(psm);
    const unsigned sA = sbase;
    const unsigned sB = sbase + 32768;
    float* smf = (float*)psm;
    const int tid = threadIdx.x, lane = tid & 31, wid = tid >> 5;
    const int wm = wid & 1, wn = wid >> 1;      // 2M x 4N
    const long m0 = (long)blockIdx.y * 128;
    const int n0 = blockIdx.x * 128;

    float acc[4][4][4];
#pragma unroll
    for (int mt = 0; mt < 4; ++mt)
#pragma unroll
        for (int nt = 0; nt < 4; ++nt)
#pragma unroll
            for (int c = 0; c < 4; ++c) acc[mt][nt][c] = 0.f;

    const int ar = tid >> 3, acq = tid & 7;
    const int br = tid >> 4, bcq = tid & 15;
    const __nv_bfloat16* Agbase = g_Yb + (m0 + ar) * (long)CDd + acq * 8;
    const __nv_bfloat16* Bgbase = g_Wpb + (long)br * Dd + n0 + bcq * 8;

    auto loadTile = [&](int kc, int buf) {
        unsigned Ab = sA + buf * 16384;
        unsigned Bb = sB + buf * 16384;
        const __nv_bfloat16* Ag = Agbase + kc * 64;
        const __nv_bfloat16* Bg = Bgbase + (long)(kc * 64) * Dd;
#pragma unroll
        for (int i = 0; i < 4; ++i) {
            int r = ar + i * 32;
            unsigned off = (unsigned)(r * 128 + acq * 16);
            cpa16(Ab + (off ^ ((r & 7) << 4)), Ag + (long)i * 32 * CDd);
        }
#pragma unroll
        for (int i = 0; i < 4; ++i) {
            int r = br + i * 16;
            unsigned off = (unsigned)(r * 256 + bcq * 16);
            cpa16(Bb + (off ^ ((r & 7) << 4)), Bg + (long)i * 16 * Dd);
        }
    };

    loadTile(0, 0);
    CP_COMMIT();

    const unsigned sw = (unsigned)((lane & 7) << 4);
    const int al = lane & 15, ah = lane >> 4;

    for (int kc = 0; kc < 8; ++kc) {
        CP_WAIT0();
        __syncthreads();
        if (kc + 1 < 8) { loadTile(kc + 1, (kc + 1) & 1); CP_COMMIT(); }

        unsigned Ab = sA + (kc & 1) * 16384;
        unsigned Bb = sB + (kc & 1) * 16384;
#pragma unroll
        for (int ks = 0; ks < 4; ++ks) {
            unsigned afr[4][4];
#pragma unroll
            for (int mt = 0; mt < 4; ++mt) {
                unsigned row = wm * 64 + mt * 16 + al;
                unsigned off = row * 128 + ks * 32 + ah * 16;
                ldm_x4(afr[mt], Ab + (off ^ sw));
            }
            unsigned bfr[2][4];
#pragma unroll
            for (int nq = 0; nq < 2; ++nq) {
                unsigned row = ks * 16 + al;
                unsigned off = row * 256 + (wn * 32 + nq * 16 + ah * 8) * 2;
                ldm_x4_t(bfr[nq], Bb + (off ^ sw));
            }
#pragma unroll
            for (int mt = 0; mt < 4; ++mt)
#pragma unroll
                for (int nq = 0; nq < 2; ++nq) {
                    mma_bf16(acc[mt][2 * nq],     afr[mt], bfr[nq][0], bfr[nq][1]);
                    mma_bf16(acc[mt][2 * nq + 1], afr[mt], bfr[nq][2], bfr[nq][3]);
                }
        }
        __syncthreads();
    }

    // stage accumulators to smem [128][132]
#pragma unroll
    for (int mt = 0; mt < 4; ++mt) {
        int r0 = wm * 64 + mt * 16 + (lane >> 2);
#pragma unroll
        for (int nt = 0; nt < 4; ++nt) {
            int c = wn * 32 + nt * 8 + 2 * (lane & 3);
            *(float2*)&smf[r0 * 132 + c]       = make_float2(acc[mt][nt][0], acc[mt][nt][1]);
            *(float2*)&smf[(r0 + 8) * 132 + c] = make_float2(acc[mt][nt][2], acc[mt][nt][3]);
        }
    }
    __syncthreads();

    // coalesced gated-residual epilogue
    const int cc = lane * 4;
    float4 gs  = *(const float4*)&g_gatesig[n0 + cc];
    float4 bpv = *(const float4*)(bp + n0 + cc);
#pragma unroll
    for (int it = 0; it < 16; ++it) {
        int rr = it * 8 + wid;
        float4 v = *(float4*)&smf[rr * 132 + cc];
        const float* xr = x + (m0 + rr) * (long)Dd + n0 + cc;
        float4 xv = *(const float4*)xr;
        float4 o;
        o.x = xv.x + gs.x * (v.x + bpv.x);
        o.y = xv.y + gs.y * (v.y + bpv.y);
        o.z = xv.z + gs.z * (v.z + bpv.z);
        o.w = xv.w + gs.w * (v.w + bpv.w);
        *(float4*)(out + (m0 + rr) * (long)Dd + n0 + cc) = o;
    }
}

// ================= launch =================
extern "C" void kernel_launch(void* const* d_in, const int* in_sizes, int n_in,
                              void* d_out, int out_size) {
    const float* x       = (const float*)d_in[0];
    const float* anchors = (const float*)d_in[1];
    const float* ln_g    = (const float*)d_in[2];
    const float* ln_b    = (const float*)d_in[3];
    const float* W1      = (const float*)d_in[4];
    const float* b1      = (const float*)d_in[5];
    const float* W2      = (const float*)d_in[6];
    const float* b2      = (const float*)d_in[7];
    const float* cg      = (const float*)d_in[8];
    const float* cb      = (const float*)d_in[9];
    const float* Wp      = (const float*)d_in[10];
    const float* bp      = (const float*)d_in[11];
    const float* gate    = (const float*)d_in[12];
    float* out = (float*)d_out;

    const int Ntok = in_sizes[0] / Dd;   // 32768

    cudaFuncSetAttribute(token_kernel, cudaFuncAttributeMaxDynamicSharedMemorySize,
                         SM_FLOATS * sizeof(float));
    cudaFuncSetAttribute(proj_kernel, cudaFuncAttributeMaxDynamicSharedMemorySize, PSM_TOTAL);

    prep_kernel<<<64 + 1 + Cc + 1, 256>>>(anchors, gate, Wp, W2);
    token_kernel<<<Ntok / TB, 256, SM_FLOATS * sizeof(float)>>>(
        x, ln_g, ln_b, W1, b1, b2, cg, cb);
    proj_kernel<<<dim3(Dd / 128, Ntok / 128), 256, PSM_TOTAL>>>(bp, x, out);
}

// round 14
// speedup vs baseline: 1.3638x; 1.0206x over previous
#include <cuda_runtime.h>
#include <cuda_bf16.h>
#include <math.h>

// Problem constants (fixed shapes)
#define Dd 1024
#define Aa 16
#define Cc 8
#define DCc 64
#define CDd 512      // C*dc
#define E2 128       // 2*dc
#define TB 32        // tokens per CTA in token_kernel
#define NMAX 32768

// -------- device scratch (no allocations allowed) --------
__device__ __align__(16) float g_gatesig[Dd];                    // sigmoid(gate)
__device__ __align__(16) __nv_bfloat16 g_Yb[(size_t)NMAX * CDd]; // 32 MB: y_flat (bf16)
__device__ __align__(16) __nv_bfloat16 g_Wpb[CDd * Dd];          // Wp in bf16 [k][n]
__device__ __align__(16) uint2 g_W2frag[Cc * 8 * 8 * 32];        // W2 in HMMA B-fragment layout
__device__ __align__(16) uint2 g_AnFrag[64 * 2 * 32];            // anchors in HMMA B-fragment layout

__device__ __forceinline__ float wsum(float v) {
#pragma unroll
    for (int o = 16; o; o >>= 1) v += __shfl_xor_sync(0xffffffffu, v, o);
    return v;
}

// -------- tensor-core helpers --------
__device__ __forceinline__ void ldm_x4(unsigned* r, unsigned addr) {
    asm volatile("ldmatrix.sync.aligned.m8n8.x4.shared.b16 {%0,%1,%2,%3}, [%4];"
        : "=r"(r[0]), "=r"(r[1]), "=r"(r[2]), "=r"(r[3]) : "r"(addr));
}
__device__ __forceinline__ void ldm_x4_t(unsigned* r, unsigned addr) {
    asm volatile("ldmatrix.sync.aligned.m8n8.x4.trans.shared.b16 {%0,%1,%2,%3}, [%4];"
        : "=r"(r[0]), "=r"(r[1]), "=r"(r[2]), "=r"(r[3]) : "r"(addr));
}
__device__ __forceinline__ void mma_bf16(float* d, const unsigned* a, unsigned b0, unsigned b1) {
    asm volatile("mma.sync.aligned.m16n8k16.row.col.f32.bf16.bf16.f32 "
        "{%0,%1,%2,%3}, {%4,%5,%6,%7}, {%8,%9}, {%0,%1,%2,%3};"
        : "+f"(d[0]), "+f"(d[1]), "+f"(d[2]), "+f"(d[3])
        : "r"(a[0]), "r"(a[1]), "r"(a[2]), "r"(a[3]), "r"(b0), "r"(b1));
}
__device__ __forceinline__ void cpa16(unsigned saddr, const void* g) {
    asm volatile("cp.async.cg.shared.global [%0], [%1], 16;" :: "r"(saddr), "l"(g));
}
#define CP_COMMIT() asm volatile("cp.async.commit_group;")
#define CP_WAIT0()  asm volatile("cp.async.wait_group 0;")

__device__ __forceinline__ unsigned pk_bf16x2(float lo, float hi) {
    __nv_bfloat162 t = __floats2bfloat162_rn(lo, hi);
    return *reinterpret_cast<unsigned*>(&t);
}

// ================= K0: prep (Wp->bf16, gate, W2 fragments, anchor fragments) =================
__global__ void prep_kernel(const float* __restrict__ anchors, const float* __restrict__ gate,
                            const float* __restrict__ Wp, const float* __restrict__ W2) {
    int tid = threadIdx.x, lane = tid & 31, wid = tid >> 5;
    if (blockIdx.x < 64) {
        int base = blockIdx.x * 8192;
#pragma unroll
        for (int j = 0; j < 8; ++j) {
            int pos = base + (tid + j * 256) * 4;
            float4 v = *(const float4*)(Wp + pos);
            __nv_bfloat162 lo = __floats2bfloat162_rn(v.x, v.y);
            __nv_bfloat162 hi = __floats2bfloat162_rn(v.z, v.w);
            *(__nv_bfloat162*)(g_Wpb + pos)     = lo;
            *(__nv_bfloat162*)(g_Wpb + pos + 2) = hi;
        }
    } else if (blockIdx.x == 64) {
        for (int i = tid; i < Dd; i += 256)
            g_gatesig[i] = 1.0f / (1.0f + expf(-gate[i]));
    } else if (blockIdx.x < 64 + 1 + Cc) {
        int k = blockIdx.x - 65;
        const float* w = W2 + (long)k * E2 * DCc;   // [128][64]
        for (int idx = tid; idx < 2048; idx += 256) {
            int kt = idx >> 8;
            int rem = idx & 255;
            int nt = rem >> 5;
            int ln = rem & 31;
            int q = ln & 3, gg = ln >> 2;
            int N = nt * 8 + gg;
            int e0 = kt * 16 + 2 * q;
            uint2 val;
            val.x = pk_bf16x2(w[e0 * 64 + N],       w[(e0 + 1) * 64 + N]);
            val.y = pk_bf16x2(w[(e0 + 8) * 64 + N], w[(e0 + 9) * 64 + N]);
            g_W2frag[((k * 8 + kt) * 8 + nt) * 32 + ln] = val;
        }
    } else {
        __shared__ float ainv[Aa];
#pragma unroll
        for (int t = 0; t < 2; ++t) {
            int a = wid * 2 + t;
            float s = 0.f;
#pragma unroll
            for (int q = 0; q < 8; ++q) {
                float4 v = *(const float4*)(anchors + a * Dd + q * 128 + lane * 4);
                s += v.x * v.x + v.y * v.y + v.z * v.z + v.w * v.w;
            }
            s = wsum(s);
            if (lane == 0) ainv[a] = 1.0f / fmaxf(sqrtf(s), 1e-12f);
        }
        __syncthreads();
        for (int e = tid; e < 64 * 2 * 32; e += 256) {
            int ln = e & 31, nt = (e >> 5) & 1, kt = e >> 6;
            int q = ln & 3, gg = ln >> 2;
            int n = nt * 8 + gg;
            int k0 = kt * 16 + 2 * q;
            float inv = ainv[n];
            uint2 val;
            val.x = pk_bf16x2(anchors[n * Dd + k0] * inv,     anchors[n * Dd + k0 + 1] * inv);
            val.y = pk_bf16x2(anchors[n * Dd + k0 + 8] * inv, anchors[n * Dd + k0 + 9] * inv);
            g_AnFrag[(kt * 2 + nt) * 32 + ln] = val;
        }
    }
}

// tiny diagnostic kernel: shifts the ncu capture window so token_kernel is sampled
__global__ void diag_kernel() {}

// ================= K1: LN/L2 -> bf16 H -> HMMA dots -> warp-per-comp HMMA MLP =================
#define OFF_H    0        // 16384 floats = 64 KB: H tile 32 x 1024 bf16 (row stride 2048 B, swizzled)
#define OFF_W1   16384
#define OFF_B1   18432
#define OFF_B2   19456
#define OFF_CG   19968
#define OFF_CB   20480
#define OFF_TRI  20992
#define OFF_LNG  21504
#define OFF_LNB  22528
#define OFF_PART 23552
#define SM_FLOATS 25600   // 102400 bytes

__global__ void __launch_bounds__(256, 2)
token_kernel(const float* __restrict__ x,
             const float* __restrict__ ln_g, const float* __restrict__ ln_b,
             const float* __restrict__ W1, const float* __restrict__ b1,
             const float* __restrict__ b2, const float* __restrict__ cg,
             const float* __restrict__ cb)
{
    extern __shared__ float sm[];
    const unsigned sbase = (unsigned)__cvta_generic_to_shared(sm);
    const int tid = threadIdx.x, lane = tid & 31, wid = tid >> 5;

    for (int t = tid; t < 512; t += 256)
        *(float4*)&sm[OFF_W1 + t * 4] = *(const float4*)&W1[t * 4];
    *(float4*)&sm[OFF_B1 + tid * 4] = *(const float4*)&b1[tid * 4];
    if (tid < 128) {
        *(float4*)&sm[OFF_B2 + tid * 4] = *(const float4*)&b2[tid * 4];
        *(float4*)&sm[OFF_CG + tid * 4] = *(const float4*)&cg[tid * 4];
        *(float4*)&sm[OFF_CB + tid * 4] = *(const float4*)&cb[tid * 4];
    }
    *(float4*)&sm[OFF_LNG + tid * 4] = *(const float4*)&ln_g[tid * 4];
    *(float4*)&sm[OFF_LNB + tid * 4] = *(const float4*)&ln_b[tid * 4];
    __syncthreads();

    const long base_tok = (long)blockIdx.x * TB;

    // ---------- Phase A: 2 tokens per warp per round; fused sum+sumsq ----------
    for (int r = 0; r < 2; ++r) {
        const int na = r * 16 + wid * 2;           // tokens na, na+1
        const float* xra = x + (base_tok + na) * (long)Dd;
        const float* xrb = xra + Dd;
        float va[32], vb[32];
#pragma unroll
        for (int q = 0; q < 8; ++q) {
            float4 ta = *(const float4*)(xra + q * 128 + lane * 4);
            float4 tb = *(const float4*)(xrb + q * 128 + lane * 4);
            va[q*4+0] = ta.x; va[q*4+1] = ta.y; va[q*4+2] = ta.z; va[q*4+3] = ta.w;
            vb[q*4+0] = tb.x; vb[q*4+1] = tb.y; vb[q*4+2] = tb.z; vb[q*4+3] = tb.w;
        }
        // L2-prefetch round 1's x rows while round 0 computes (zero reg cost)
        if (r == 0) {
            const float* pre = x + (base_tok + 16 + wid * 2) * (long)Dd;
#pragma unroll
            for (int q = 0; q < 8; ++q) {
                asm volatile("prefetch.global.L2 [%0];" :: "l"(pre + q * 128 + lane * 4));
                asm volatile("prefetch.global.L2 [%0];" :: "l"(pre + Dd + q * 128 + lane * 4));
            }
        }
        float sa = 0.f, qa = 0.f, sb = 0.f, qb = 0.f;
#pragma unroll
        for (int i = 0; i < 32; ++i) {
            sa += va[i]; qa = fmaf(va[i], va[i], qa);
            sb += vb[i]; qb = fmaf(vb[i], vb[i], qb);
        }
#pragma unroll
        for (int o = 16; o; o >>= 1) {
            sa += __shfl_xor_sync(0xffffffffu, sa, o);
            sb += __shfl_xor_sync(0xffffffffu, sb, o);
            qa += __shfl_xor_sync(0xffffffffu, qa, o);
            qb += __shfl_xor_sync(0xffffffffu, qb, o);
        }
        const float mua = sa * (1.0f / Dd), mub = sb * (1.0f / Dd);
        const float rsa = rsqrtf(fmaxf(qa * (1.0f / Dd) - mua * mua, 0.f) + 1e-5f);
        const float rsb = rsqrtf(fmaxf(qb * (1.0f / Dd) - mub * mub, 0.f) + 1e-5f);

        float n2a = 0.f, n2b = 0.f;
#pragma unroll
        for (int q = 0; q < 8; ++q) {
            float4 gv = *(const float4*)&sm[OFF_LNG + q * 128 + lane * 4];
            float4 bv = *(const float4*)&sm[OFF_LNB + q * 128 + lane * 4];
            float a0 = (va[q*4+0] - mua) * rsa * gv.x + bv.x;
            float a1 = (va[q*4+1] - mua) * rsa * gv.y + bv.y;
            float a2 = (va[q*4+2] - mua) * rsa * gv.z + bv.z;
            float a3 = (va[q*4+3] - mua) * rsa * gv.w + bv.w;
            float c0 = (vb[q*4+0] - mub) * rsb * gv.x + bv.x;
            float c1 = (vb[q*4+1] - mub) * rsb * gv.y + bv.y;
            float c2 = (vb[q*4+2] - mub) * rsb * gv.z + bv.z;
            float c3 = (vb[q*4+3] - mub) * rsb * gv.w + bv.w;
            va[q*4+0] = a0; va[q*4+1] = a1; va[q*4+2] = a2; va[q*4+3] = a3;
            vb[q*4+0] = c0; vb[q*4+1] = c1; vb[q*4+2] = c2; vb[q*4+3] = c3;
            n2a += a0*a0 + a1*a1 + a2*a2 + a3*a3;
            n2b += c0*c0 + c1*c1 + c2*c2 + c3*c3;
        }
#pragma unroll
        for (int o = 16; o; o >>= 1) {
            n2a += __shfl_xor_sync(0xffffffffu, n2a, o);
            n2b += __shfl_xor_sync(0xffffffffu, n2b, o);
        }
        const float inva = 1.0f / fmaxf(sqrtf(n2a), 1e-12f);
        const float invb = 1.0f / fmaxf(sqrtf(n2b), 1e-12f);

        char* hra = (char*)sm + na * 2048;
        char* hrb = hra + 2048;
        const unsigned swa = (unsigned)((na & 7) << 4);
        const unsigned swb = (unsigned)(((na + 1) & 7) << 4);
#pragma unroll
        for (int q = 0; q < 8; ++q) {
            unsigned off = (unsigned)(q * 256 + lane * 8);
            *(uint2*)(hra + (off ^ swa)) =
                make_uint2(pk_bf16x2(va[q*4+0]*inva, va[q*4+1]*inva),
                           pk_bf16x2(va[q*4+2]*inva, va[q*4+3]*inva));
            *(uint2*)(hrb + (off ^ swb)) =
                make_uint2(pk_bf16x2(vb[q*4+0]*invb, vb[q*4+1]*invb),
                           pk_bf16x2(vb[q*4+2]*invb, vb[q*4+3]*invb));
        }
    }
    __syncthreads();

    // ---------- Phase A2: tri = 1 - H @ Anchors^T via HMMA ----------
    {
        const int mt = wid & 1;
        const int kq = wid >> 1;
        const int al = lane & 15, ah = lane >> 4;
        const unsigned rowb = (unsigned)(mt * 16 + al);
        const unsigned rowoff = rowb * 2048;
        const unsigned swz = (rowb & 7) << 4;

        float acc[2][4];
#pragma unroll
        for (int nt = 0; nt < 2; ++nt)
#pragma unroll
            for (int c = 0; c < 4; ++c) acc[nt][c] = 0.f;

#pragma unroll
        for (int s = 0; s < 16; ++s) {
            const int kt = kq * 16 + s;
            unsigned afr[4];
            unsigned off = rowoff + (((unsigned)(kt * 32 + ah * 16)) ^ swz);
            ldm_x4(afr, sbase + off);
            uint2 b0 = g_AnFrag[(kt * 2 + 0) * 32 + lane];
            uint2 b1 = g_AnFrag[(kt * 2 + 1) * 32 + lane];
            mma_bf16(acc[0], afr, b0.x, b0.y);
            mma_bf16(acc[1], afr, b1.x, b1.y);
        }
        float* P = &sm[OFF_PART + kq * 512];
        const int r0 = mt * 16 + (lane >> 2);
        const int c0 = 2 * (lane & 3);
        P[r0 * 16 + c0]           = acc[0][0];
        P[r0 * 16 + c0 + 1]       = acc[0][1];
        P[(r0 + 8) * 16 + c0]     = acc[0][2];
        P[(r0 + 8) * 16 + c0 + 1] = acc[0][3];
        P[r0 * 16 + 8 + c0]           = acc[1][0];
        P[r0 * 16 + 8 + c0 + 1]       = acc[1][1];
        P[(r0 + 8) * 16 + 8 + c0]     = acc[1][2];
        P[(r0 + 8) * 16 + 8 + c0 + 1] = acc[1][3];
    }
    __syncthreads();
    for (int t = tid; t < 512; t += 256) {
        float d = sm[OFF_PART + t] + sm[OFF_PART + 512 + t]
                + sm[OFF_PART + 1024 + t] + sm[OFF_PART + 1536 + t];
        sm[OFF_TRI + t] = 1.0f - d;
    }
    __syncthreads();

    // ---------- Phase B: warp w = compartment w ----------
    {
        const int k = wid;
        const int q = lane & 3, rr = lane >> 2;

        float g00[2], g01[2], g10[2], g11[2];
#pragma unroll
        for (int mt = 0; mt < 2; ++mt) {
            int n0 = mt * 16 + rr;
            g00[mt] = sm[OFF_TRI + n0 * 16 + k];
            g01[mt] = sm[OFF_TRI + n0 * 16 + 8 + k];
            g10[mt] = sm[OFF_TRI + (n0 + 8) * 16 + k];
            g11[mt] = sm[OFF_TRI + (n0 + 8) * 16 + 8 + k];
        }

        float acc[2][8][4];
#pragma unroll
        for (int mt = 0; mt < 2; ++mt)
#pragma unroll
            for (int nt = 0; nt < 8; ++nt)
#pragma unroll
                for (int c = 0; c < 4; ++c) acc[mt][nt][c] = 0.f;

        const float* W1a = &sm[OFF_W1 + (k * 2 + 0) * E2];
        const float* W1b = &sm[OFF_W1 + (k * 2 + 1) * E2];
        const float* B1  = &sm[OFF_B1 + k * E2];

#pragma unroll
        for (int kt = 0; kt < 8; ++kt) {
            const int e0 = kt * 16 + 2 * q;
            float wa0 = W1a[e0], wa1 = W1a[e0+1], wa8 = W1a[e0+8], wa9 = W1a[e0+9];
            float wb0 = W1b[e0], wb1 = W1b[e0+1], wb8 = W1b[e0+8], wb9 = W1b[e0+9];
            float bb0 = B1[e0],  bb1 = B1[e0+1],  bb8 = B1[e0+8],  bb9 = B1[e0+9];

            unsigned afr[2][4];
#pragma unroll
            for (int mt = 0; mt < 2; ++mt) {
                float a0 = g00[mt], a1 = g01[mt], c0 = g10[mt], c1 = g11[mt];
                float t;
                t = fmaxf(a0*wa0 + a1*wb0 + bb0, 0.f); float u00 = t*t;
                t = fmaxf(a0*wa1 + a1*wb1 + bb1, 0.f); float u01 = t*t;
                t = fmaxf(a0*wa8 + a1*wb8 + bb8, 0.f); float u08 = t*t;
                t = fmaxf(a0*wa9 + a1*wb9 + bb9, 0.f); float u09 = t*t;
                t = fmaxf(c0*wa0 + c1*wb0 + bb0, 0.f); float u10 = t*t;
                t = fmaxf(c0*wa1 + c1*wb1 + bb1, 0.f); float u11 = t*t;
                t = fmaxf(c0*wa8 + c1*wb8 + bb8, 0.f); float u18 = t*t;
                t = fmaxf(c0*wa9 + c1*wb9 + bb9, 0.f); float u19 = t*t;
                afr[mt][0] = pk_bf16x2(u00, u01);
                afr[mt][1] = pk_bf16x2(u10, u11);
                afr[mt][2] = pk_bf16x2(u08, u09);
                afr[mt][3] = pk_bf16x2(u18, u19);
            }
            const uint2* Bf = &g_W2frag[((k * 8 + kt) * 8) * 32 + lane];
#pragma unroll
            for (int nt = 0; nt < 8; ++nt) {
                uint2 b = Bf[nt * 32];
                mma_bf16(acc[0][nt], afr[0], b.x, b.y);
                mma_bf16(acc[1][nt], afr[1], b.x, b.y);
            }
        }

        const float* B2 = &sm[OFF_B2 + k * 64];
        const float* CG = &sm[OFF_CG + k * 64];
        const float* CB = &sm[OFF_CB + k * 64];
#pragma unroll
        for (int mt = 0; mt < 2; ++mt) {
            float s0 = 0.f, s1 = 0.f;
#pragma unroll
            for (int nt = 0; nt < 8; ++nt) {
                float2 b2v = *(const float2*)&B2[nt * 8 + 2 * q];
                acc[mt][nt][0] += b2v.x; acc[mt][nt][1] += b2v.y;
                acc[mt][nt][2] += b2v.x; acc[mt][nt][3] += b2v.y;
                s0 += acc[mt][nt][0] + acc[mt][nt][1];
                s1 += acc[mt][nt][2] + acc[mt][nt][3];
            }
            s0 += __shfl_xor_sync(0xffffffffu, s0, 1);
            s0 += __shfl_xor_sync(0xffffffffu, s0, 2);
            s1 += __shfl_xor_sync(0xffffffffu, s1, 1);
            s1 += __shfl_xor_sync(0xffffffffu, s1, 2);
            float mu0 = s0 * (1.0f / 64.0f), mu1 = s1 * (1.0f / 64.0f);
            float v0 = 0.f, v1 = 0.f;
#pragma unroll
            for (int nt = 0; nt < 8; ++nt) {
                float d0 = acc[mt][nt][0] - mu0, d1 = acc[mt][nt][1] - mu0;
                float d2 = acc[mt][nt][2] - mu1, d3 = acc[mt][nt][3] - mu1;
                v0 += d0 * d0 + d1 * d1;
                v1 += d2 * d2 + d3 * d3;
            }
            v0 += __shfl_xor_sync(0xffffffffu, v0, 1);
            v0 += __shfl_xor_sync(0xffffffffu, v0, 2);
            v1 += __shfl_xor_sync(0xffffffffu, v1, 1);
            v1 += __shfl_xor_sync(0xffffffffu, v1, 2);
            float r0 = rsqrtf(v0 * (1.0f / 64.0f) + 1e-5f);
            float r1 = rsqrtf(v1 * (1.0f / 64.0f) + 1e-5f);

            long n0 = base_tok + mt * 16 + rr;
            __nv_bfloat16* y0 = g_Yb + n0 * (long)CDd + k * 64;
            __nv_bfloat16* y1 = y0 + 8 * (long)CDd;
#pragma unroll
            for (int nt = 0; nt < 8; ++nt) {
                int col = nt * 8 + 2 * q;
                float2 cgv = *(const float2*)&CG[col];
                float2 cbv = *(const float2*)&CB[col];
                unsigned p0 = pk_bf16x2((acc[mt][nt][0] - mu0) * r0 * cgv.x + cbv.x,
                                        (acc[mt][nt][1] - mu0) * r0 * cgv.y + cbv.y);
                unsigned p1 = pk_bf16x2((acc[mt][nt][2] - mu1) * r1 * cgv.x + cbv.x,
                                        (acc[mt][nt][3] - mu1) * r1 * cgv.y + cbv.y);
                *(unsigned*)(y0 + col) = p0;
                *(unsigned*)(y1 + col) = p1;
            }
        }
    }
}

// ================= K2: bf16 HMMA projection GEMM + gated residual (proven config) =================
#define PSM_TOTAL 68608

__global__ void __launch_bounds__(256)
proj_kernel(const float* __restrict__ bp, const float* __restrict__ x, float* __restrict__ out)
{
    extern __shared__ char psm[];
    const unsigned sbase = (unsigned)__cvta_generic_to_shared(psm);
    const unsigned sA = sbase;
    const unsigned sB = sbase + 32768;
    float* smf = (float*)psm;
    const int tid = threadIdx.x, lane = tid & 31, wid = tid >> 5;
    const int wm = wid & 1, wn = wid >> 1;      // 2M x 4N
    const long m0 = (long)blockIdx.y * 128;
    const int n0 = blockIdx.x * 128;

    float acc[4][4][4];
#pragma unroll
    for (int mt = 0; mt < 4; ++mt)
#pragma unroll
        for (int nt = 0; nt < 4; ++nt)
#pragma unroll
            for (int c = 0; c < 4; ++c) acc[mt][nt][c] = 0.f;

    const int ar = tid >> 3, acq = tid & 7;
    const int br = tid >> 4, bcq = tid & 15;
    const __nv_bfloat16* Agbase = g_Yb + (m0 + ar) * (long)CDd + acq * 8;
    const __nv_bfloat16* Bgbase = g_Wpb + (long)br * Dd + n0 + bcq * 8;

    auto loadTile = [&](int kc, int buf) {
        unsigned Ab = sA + buf * 16384;
        unsigned Bb = sB + buf * 16384;
        const __nv_bfloat16* Ag = Agbase + kc * 64;
        const __nv_bfloat16* Bg = Bgbase + (long)(kc * 64) * Dd;
#pragma unroll
        for (int i = 0; i < 4; ++i) {
            int r = ar + i * 32;
            unsigned off = (unsigned)(r * 128 + acq * 16);
            cpa16(Ab + (off ^ ((r & 7) << 4)), Ag + (long)i * 32 * CDd);
        }
#pragma unroll
        for (int i = 0; i < 4; ++i) {
            int r = br + i * 16;
            unsigned off = (unsigned)(r * 256 + bcq * 16);
            cpa16(Bb + (off ^ ((r & 7) << 4)), Bg + (long)i * 16 * Dd);
        }
    };

    loadTile(0, 0);
    CP_COMMIT();

    const unsigned sw = (unsigned)((lane & 7) << 4);
    const int al = lane & 15, ah = lane >> 4;

    for (int kc = 0; kc < 8; ++kc) {
        CP_WAIT0();
        __syncthreads();
        if (kc + 1 < 8) { loadTile(kc + 1, (kc + 1) & 1); CP_COMMIT(); }

        unsigned Ab = sA + (kc & 1) * 16384;
        unsigned Bb = sB + (kc & 1) * 16384;
#pragma unroll
        for (int ks = 0; ks < 4; ++ks) {
            unsigned afr[4][4];
#pragma unroll
            for (int mt = 0; mt < 4; ++mt) {
                unsigned row = wm * 64 + mt * 16 + al;
                unsigned off = row * 128 + ks * 32 + ah * 16;
                ldm_x4(afr[mt], Ab + (off ^ sw));
            }
            unsigned bfr[2][4];
#pragma unroll
            for (int nq = 0; nq < 2; ++nq) {
                unsigned row = ks * 16 + al;
                unsigned off = row * 256 + (wn * 32 + nq * 16 + ah * 8) * 2;
                ldm_x4_t(bfr[nq], Bb + (off ^ sw));
            }
#pragma unroll
            for (int mt = 0; mt < 4; ++mt)
#pragma unroll
                for (int nq = 0; nq < 2; ++nq) {
                    mma_bf16(acc[mt][2 * nq],     afr[mt], bfr[nq][0], bfr[nq][1]);
                    mma_bf16(acc[mt][2 * nq + 1], afr[mt], bfr[nq][2], bfr[nq][3]);
                }
        }
        __syncthreads();
    }

    // stage accumulators to smem [128][132]
#pragma unroll
    for (int mt = 0; mt < 4; ++mt) {
        int r0 = wm * 64 + mt * 16 + (lane >> 2);
#pragma unroll
        for (int nt = 0; nt < 4; ++nt) {
            int c = wn * 32 + nt * 8 + 2 * (lane & 3);
            *(float2*)&smf[r0 * 132 + c]       = make_float2(acc[mt][nt][0], acc[mt][nt][1]);
            *(float2*)&smf[(r0 + 8) * 132 + c] = make_float2(acc[mt][nt][2], acc[mt][nt][3]);
        }
    }
    __syncthreads();

    // coalesced gated-residual epilogue
    const int cc = lane * 4;
    float4 gs  = *(const float4*)&g_gatesig[n0 + cc];
    float4 bpv = *(const float4*)(bp + n0 + cc);
#pragma unroll
    for (int it = 0; it < 16; ++it) {
        int rr = it * 8 + wid;
        float4 v = *(float4*)&smf[rr * 132 + cc];
        const float* xr = x + (m0 + rr) * (long)Dd + n0 + cc;
        float4 xv = *(const float4*)xr;
        float4 o;
        o.x = xv.x + gs.x * (v.x + bpv.x);
        o.y = xv.y + gs.y * (v.y + bpv.y);
        o.z = xv.z + gs.z * (v.z + bpv.z);
        o.w = xv.w + gs.w * (v.w + bpv.w);
        *(float4*)(out + (m0 + rr) * (long)Dd + n0 + cc) = o;
    }
}

// ================= launch =================
extern "C" void kernel_launch(void* const* d_in, const int* in_sizes, int n_in,
                              void* d_out, int out_size) {
    const float* x       = (const float*)d_in[0];
    const float* anchors = (const float*)d_in[1];
    const float* ln_g    = (const float*)d_in[2];
    const float* ln_b    = (const float*)d_in[3];
    const float* W1      = (const float*)d_in[4];
    const float* b1      = (const float*)d_in[5];
    const float* W2      = (const float*)d_in[6];
    const float* b2      = (const float*)d_in[7];
    const float* cg      = (const float*)d_in[8];
    const float* cb      = (const float*)d_in[9];
    const float* Wp      = (const float*)d_in[10];
    const float* bp      = (const float*)d_in[11];
    const float* gate    = (const float*)d_in[12];
    float* out = (float*)d_out;

    const int Ntok = in_sizes[0] / Dd;   // 32768

    cudaFuncSetAttribute(token_kernel, cudaFuncAttributeMaxDynamicSharedMemorySize,
                         SM_FLOATS * sizeof(float));
    cudaFuncSetAttribute(proj_kernel, cudaFuncAttributeMaxDynamicSharedMemorySize, PSM_TOTAL);

    prep_kernel<<<64 + 1 + Cc + 1, 256>>>(anchors, gate, Wp, W2);
    token_kernel<<<Ntok / TB, 256, SM_FLOATS * sizeof(float)>>>(
        x, ln_g, ln_b, W1, b1, b2, cg, cb);
    diag_kernel<<<1, 32>>>();   // shifts ncu's sampled launch onto token_kernel
    proj_kernel<<<dim3(Dd / 128, Ntok / 128), 256, PSM_TOTAL>>>(bp, x, out);
}

// round 15
// speedup vs baseline: 1.3643x; 1.0003x over previous
#include <cuda_runtime.h>
#include <cuda_bf16.h>
#include <math.h>

// Problem constants (fixed shapes)
#define Dd 1024
#define Aa 16
#define Cc 8
#define DCc 64
#define CDd 512      // C*dc
#define E2 128       // 2*dc
#define TB 16        // tokens per CTA in token_kernel (3 CTAs/SM)
#define NMAX 32768

// -------- device scratch (no allocations allowed) --------
__device__ __align__(16) float g_gatesig[Dd];                    // sigmoid(gate)
__device__ __align__(16) __nv_bfloat16 g_Yb[(size_t)NMAX * CDd]; // 32 MB: y_flat (bf16)
__device__ __align__(16) __nv_bfloat16 g_Wpb[CDd * Dd];          // Wp in bf16 [k][n]
__device__ __align__(16) uint2 g_W2frag[Cc * 8 * 8 * 32];        // W2 in HMMA B-fragment layout
__device__ __align__(16) uint2 g_AnFrag[64 * 2 * 32];            // anchors in HMMA B-fragment layout

__device__ __forceinline__ float wsum(float v) {
#pragma unroll
    for (int o = 16; o; o >>= 1) v += __shfl_xor_sync(0xffffffffu, v, o);
    return v;
}

// -------- tensor-core helpers --------
__device__ __forceinline__ void ldm_x4(unsigned* r, unsigned addr) {
    asm volatile("ldmatrix.sync.aligned.m8n8.x4.shared.b16 {%0,%1,%2,%3}, [%4];"
        : "=r"(r[0]), "=r"(r[1]), "=r"(r[2]), "=r"(r[3]) : "r"(addr));
}
__device__ __forceinline__ void ldm_x4_t(unsigned* r, unsigned addr) {
    asm volatile("ldmatrix.sync.aligned.m8n8.x4.trans.shared.b16 {%0,%1,%2,%3}, [%4];"
        : "=r"(r[0]), "=r"(r[1]), "=r"(r[2]), "=r"(r[3]) : "r"(addr));
}
__device__ __forceinline__ void mma_bf16(float* d, const unsigned* a, unsigned b0, unsigned b1) {
    asm volatile("mma.sync.aligned.m16n8k16.row.col.f32.bf16.bf16.f32 "
        "{%0,%1,%2,%3}, {%4,%5,%6,%7}, {%8,%9}, {%0,%1,%2,%3};"
        : "+f"(d[0]), "+f"(d[1]), "+f"(d[2]), "+f"(d[3])
        : "r"(a[0]), "r"(a[1]), "r"(a[2]), "r"(a[3]), "r"(b0), "r"(b1));
}
__device__ __forceinline__ void cpa16(unsigned saddr, const void* g) {
    asm volatile("cp.async.cg.shared.global [%0], [%1], 16;" :: "r"(saddr), "l"(g));
}
#define CP_COMMIT() asm volatile("cp.async.commit_group;")
#define CP_WAIT0()  asm volatile("cp.async.wait_group 0;")

__device__ __forceinline__ unsigned pk_bf16x2(float lo, float hi) {
    __nv_bfloat162 t = __floats2bfloat162_rn(lo, hi);
    return *reinterpret_cast<unsigned*>(&t);
}

// ================= K0: prep (Wp->bf16, gate, W2 fragments, anchor fragments) =================
__global__ void prep_kernel(const float* __restrict__ anchors, const float* __restrict__ gate,
                            const float* __restrict__ Wp, const float* __restrict__ W2) {
    int tid = threadIdx.x, lane = tid & 31, wid = tid >> 5;
    if (blockIdx.x < 64) {
        int base = blockIdx.x * 8192;
#pragma unroll
        for (int j = 0; j < 8; ++j) {
            int pos = base + (tid + j * 256) * 4;
            float4 v = *(const float4*)(Wp + pos);
            __nv_bfloat162 lo = __floats2bfloat162_rn(v.x, v.y);
            __nv_bfloat162 hi = __floats2bfloat162_rn(v.z, v.w);
            *(__nv_bfloat162*)(g_Wpb + pos)     = lo;
            *(__nv_bfloat162*)(g_Wpb + pos + 2) = hi;
        }
    } else if (blockIdx.x == 64) {
        for (int i = tid; i < Dd; i += 256)
            g_gatesig[i] = 1.0f / (1.0f + expf(-gate[i]));
    } else if (blockIdx.x < 64 + 1 + Cc) {
        int k = blockIdx.x - 65;
        const float* w = W2 + (long)k * E2 * DCc;   // [128][64]
        for (int idx = tid; idx < 2048; idx += 256) {
            int kt = idx >> 8;
            int rem = idx & 255;
            int nt = rem >> 5;
            int ln = rem & 31;
            int q = ln & 3, gg = ln >> 2;
            int N = nt * 8 + gg;
            int e0 = kt * 16 + 2 * q;
            uint2 val;
            val.x = pk_bf16x2(w[e0 * 64 + N],       w[(e0 + 1) * 64 + N]);
            val.y = pk_bf16x2(w[(e0 + 8) * 64 + N], w[(e0 + 9) * 64 + N]);
            g_W2frag[((k * 8 + kt) * 8 + nt) * 32 + ln] = val;
        }
    } else {
        __shared__ float ainv[Aa];
#pragma unroll
        for (int t = 0; t < 2; ++t) {
            int a = wid * 2 + t;
            float s = 0.f;
#pragma unroll
            for (int q = 0; q < 8; ++q) {
                float4 v = *(const float4*)(anchors + a * Dd + q * 128 + lane * 4);
                s += v.x * v.x + v.y * v.y + v.z * v.z + v.w * v.w;
            }
            s = wsum(s);
            if (lane == 0) ainv[a] = 1.0f / fmaxf(sqrtf(s), 1e-12f);
        }
        __syncthreads();
        for (int e = tid; e < 64 * 2 * 32; e += 256) {
            int ln = e & 31, nt = (e >> 5) & 1, kt = e >> 6;
            int q = ln & 3, gg = ln >> 2;
            int n = nt * 8 + gg;
            int k0 = kt * 16 + 2 * q;
            float inv = ainv[n];
            uint2 val;
            val.x = pk_bf16x2(anchors[n * Dd + k0] * inv,     anchors[n * Dd + k0 + 1] * inv);
            val.y = pk_bf16x2(anchors[n * Dd + k0 + 8] * inv, anchors[n * Dd + k0 + 9] * inv);
            g_AnFrag[(kt * 2 + nt) * 32 + ln] = val;
        }
    }
}

// ================= K1: TB=16 tokens/CTA, 3 CTAs/SM =================
// smem layout (floats):
#define OFF_H    0        // 8192: H tile 16 x 1024 bf16 (row stride 2048 B, swizzled)
#define OFF_W1   8192     // 2048
#define OFF_B1   10240    // 1024
#define OFF_B2   11264    // 512
#define OFF_CG   11776    // 512
#define OFF_CB   12288    // 512
#define OFF_TRI  12800    // 256 (16x16)
#define OFF_LNG  13056    // 1024
#define OFF_LNB  14080    // 1024
#define OFF_PART 15104    // 2048 (8 kq x 16 tok x 16 anch)
#define SM_FLOATS 17152   // 68608 bytes -> 3 CTAs/SM

__global__ void __launch_bounds__(256, 3)
token_kernel(const float* __restrict__ x,
             const float* __restrict__ ln_g, const float* __restrict__ ln_b,
             const float* __restrict__ W1, const float* __restrict__ b1,
             const float* __restrict__ b2, const float* __restrict__ cg,
             const float* __restrict__ cb)
{
    extern __shared__ float sm[];
    const unsigned sbase = (unsigned)__cvta_generic_to_shared(sm);
    const int tid = threadIdx.x, lane = tid & 31, wid = tid >> 5;

    for (int t = tid; t < 512; t += 256)
        *(float4*)&sm[OFF_W1 + t * 4] = *(const float4*)&W1[t * 4];
    *(float4*)&sm[OFF_B1 + tid * 4] = *(const float4*)&b1[tid * 4];
    if (tid < 128) {
        *(float4*)&sm[OFF_B2 + tid * 4] = *(const float4*)&b2[tid * 4];
        *(float4*)&sm[OFF_CG + tid * 4] = *(const float4*)&cg[tid * 4];
        *(float4*)&sm[OFF_CB + tid * 4] = *(const float4*)&cb[tid * 4];
    }
    *(float4*)&sm[OFF_LNG + tid * 4] = *(const float4*)&ln_g[tid * 4];
    *(float4*)&sm[OFF_LNB + tid * 4] = *(const float4*)&ln_b[tid * 4];
    __syncthreads();

    const long base_tok = (long)blockIdx.x * TB;

    // ---------- Phase A: 1 token per warp per round; fused sum+sumsq; 2 rounds ----------
    for (int r = 0; r < 2; ++r) {
        const int n = r * 8 + wid;
        const float* xr = x + (base_tok + n) * (long)Dd;
        float v[32];
#pragma unroll
        for (int q = 0; q < 8; ++q) {
            float4 t4 = *(const float4*)(xr + q * 128 + lane * 4);
            v[q*4+0] = t4.x; v[q*4+1] = t4.y; v[q*4+2] = t4.z; v[q*4+3] = t4.w;
        }
        // prefetch next round's token row into L2 while round 0 computes
        if (r == 0) {
            const float* pre = x + (base_tok + 8 + wid) * (long)Dd;
#pragma unroll
            for (int q = 0; q < 8; ++q)
                asm volatile("prefetch.global.L2 [%0];" :: "l"(pre + q * 128 + lane * 4));
        }
        float s = 0.f, qq = 0.f;
#pragma unroll
        for (int i = 0; i < 32; ++i) { s += v[i]; qq = fmaf(v[i], v[i], qq); }
#pragma unroll
        for (int o = 16; o; o >>= 1) {
            s  += __shfl_xor_sync(0xffffffffu, s, o);
            qq += __shfl_xor_sync(0xffffffffu, qq, o);
        }
        const float mu = s * (1.0f / Dd);
        const float rstd = rsqrtf(fmaxf(qq * (1.0f / Dd) - mu * mu, 0.f) + 1e-5f);
        float n2 = 0.f;
#pragma unroll
        for (int q = 0; q < 8; ++q) {
            float4 gv = *(const float4*)&sm[OFF_LNG + q * 128 + lane * 4];
            float4 bv = *(const float4*)&sm[OFF_LNB + q * 128 + lane * 4];
            float a0 = (v[q*4+0] - mu) * rstd * gv.x + bv.x;
            float a1 = (v[q*4+1] - mu) * rstd * gv.y + bv.y;
            float a2 = (v[q*4+2] - mu) * rstd * gv.z + bv.z;
            float a3 = (v[q*4+3] - mu) * rstd * gv.w + bv.w;
            v[q*4+0] = a0; v[q*4+1] = a1; v[q*4+2] = a2; v[q*4+3] = a3;
            n2 += a0 * a0 + a1 * a1 + a2 * a2 + a3 * a3;
        }
        n2 = wsum(n2);
        const float inv = 1.0f / fmaxf(sqrtf(n2), 1e-12f);

        char* hrow = (char*)sm + n * 2048;
        const unsigned swz = (unsigned)((n & 7) << 4);
#pragma unroll
        for (int q = 0; q < 8; ++q) {
            unsigned p0 = pk_bf16x2(v[q*4+0] * inv, v[q*4+1] * inv);
            unsigned p1 = pk_bf16x2(v[q*4+2] * inv, v[q*4+3] * inv);
            unsigned off = (unsigned)(q * 256 + lane * 8) ^ swz;
            *(uint2*)(hrow + off) = make_uint2(p0, p1);
        }
    }
    __syncthreads();

    // ---------- Phase A2: tri = 1 - H @ Anchors^T; warp w = K-slice w ----------
    {
        const int kq = wid;                      // 8 slices x 128 dims
        const int al = lane & 15, ah = lane >> 4;
        const unsigned rowoff = (unsigned)al * 2048;
        const unsigned swz = (al & 7) << 4;

        float acc[2][4];
#pragma unroll
        for (int nt = 0; nt < 2; ++nt)
#pragma unroll
            for (int c = 0; c < 4; ++c) acc[nt][c] = 0.f;

#pragma unroll
        for (int s = 0; s < 8; ++s) {
            const int kt = kq * 8 + s;
            unsigned afr[4];
            unsigned off = rowoff + (((unsigned)(kt * 32 + ah * 16)) ^ swz);
            ldm_x4(afr, sbase + off);
            uint2 b0 = g_AnFrag[(kt * 2 + 0) * 32 + lane];
            uint2 b1 = g_AnFrag[(kt * 2 + 1) * 32 + lane];
            mma_bf16(acc[0], afr, b0.x, b0.y);
            mma_bf16(acc[1], afr, b1.x, b1.y);
        }
        float* P = &sm[OFF_PART + kq * 256];
        const int r0 = lane >> 2;
        const int c0 = 2 * (lane & 3);
        P[r0 * 16 + c0]           = acc[0][0];
        P[r0 * 16 + c0 + 1]       = acc[0][1];
        P[(r0 + 8) * 16 + c0]     = acc[0][2];
        P[(r0 + 8) * 16 + c0 + 1] = acc[0][3];
        P[r0 * 16 + 8 + c0]           = acc[1][0];
        P[r0 * 16 + 8 + c0 + 1]       = acc[1][1];
        P[(r0 + 8) * 16 + 8 + c0]     = acc[1][2];
        P[(r0 + 8) * 16 + 8 + c0 + 1] = acc[1][3];
    }
    __syncthreads();
    if (tid < 256) {
        int t = tid;
        if (t < 256) {
            float d = 0.f;
#pragma unroll
            for (int p = 0; p < 8; ++p) d += sm[OFF_PART + p * 256 + t];
            sm[OFF_TRI + t] = 1.0f - d;
        }
    }
    __syncthreads();

    // ---------- Phase B: warp w = compartment w (16 tokens) ----------
    {
        const int k = wid;
        const int q = lane & 3, rr = lane >> 2;

        float g00 = sm[OFF_TRI + rr * 16 + k];
        float g01 = sm[OFF_TRI + rr * 16 + 8 + k];
        float g10 = sm[OFF_TRI + (rr + 8) * 16 + k];
        float g11 = sm[OFF_TRI + (rr + 8) * 16 + 8 + k];

        float acc[8][4];
#pragma unroll
        for (int nt = 0; nt < 8; ++nt)
#pragma unroll
            for (int c = 0; c < 4; ++c) acc[nt][c] = 0.f;

        const float* W1a = &sm[OFF_W1 + (k * 2 + 0) * E2];
        const float* W1b = &sm[OFF_W1 + (k * 2 + 1) * E2];
        const float* B1  = &sm[OFF_B1 + k * E2];

#pragma unroll
        for (int kt = 0; kt < 8; ++kt) {
            const int e0 = kt * 16 + 2 * q;
            float wa0 = W1a[e0], wa1 = W1a[e0+1], wa8 = W1a[e0+8], wa9 = W1a[e0+9];
            float wb0 = W1b[e0], wb1 = W1b[e0+1], wb8 = W1b[e0+8], wb9 = W1b[e0+9];
            float bb0 = B1[e0],  bb1 = B1[e0+1],  bb8 = B1[e0+8],  bb9 = B1[e0+9];

            unsigned afr[4];
            float t;
            t = fmaxf(g00*wa0 + g01*wb0 + bb0, 0.f); float u00 = t*t;
            t = fmaxf(g00*wa1 + g01*wb1 + bb1, 0.f); float u01 = t*t;
            t = fmaxf(g00*wa8 + g01*wb8 + bb8, 0.f); float u08 = t*t;
            t = fmaxf(g00*wa9 + g01*wb9 + bb9, 0.f); float u09 = t*t;
            t = fmaxf(g10*wa0 + g11*wb0 + bb0, 0.f); float u10 = t*t;
            t = fmaxf(g10*wa1 + g11*wb1 + bb1, 0.f); float u11 = t*t;
            t = fmaxf(g10*wa8 + g11*wb8 + bb8, 0.f); float u18 = t*t;
            t = fmaxf(g10*wa9 + g11*wb9 + bb9, 0.f); float u19 = t*t;
            afr[0] = pk_bf16x2(u00, u01);
            afr[1] = pk_bf16x2(u10, u11);
            afr[2] = pk_bf16x2(u08, u09);
            afr[3] = pk_bf16x2(u18, u19);

            const uint2* Bf = &g_W2frag[((k * 8 + kt) * 8) * 32 + lane];
#pragma unroll
            for (int nt = 0; nt < 8; ++nt) {
                uint2 b = Bf[nt * 32];
                mma_bf16(acc[nt], afr, b.x, b.y);
            }
        }

        const float* B2 = &sm[OFF_B2 + k * 64];
        const float* CG = &sm[OFF_CG + k * 64];
        const float* CB = &sm[OFF_CB + k * 64];
        float s0 = 0.f, s1 = 0.f;
#pragma unroll
        for (int nt = 0; nt < 8; ++nt) {
            float2 b2v = *(const float2*)&B2[nt * 8 + 2 * q];
            acc[nt][0] += b2v.x; acc[nt][1] += b2v.y;
            acc[nt][2] += b2v.x; acc[nt][3] += b2v.y;
            s0 += acc[nt][0] + acc[nt][1];
            s1 += acc[nt][2] + acc[nt][3];
        }
        s0 += __shfl_xor_sync(0xffffffffu, s0, 1);
        s0 += __shfl_xor_sync(0xffffffffu, s0, 2);
        s1 += __shfl_xor_sync(0xffffffffu, s1, 1);
        s1 += __shfl_xor_sync(0xffffffffu, s1, 2);
        float mu0 = s0 * (1.0f / 64.0f), mu1 = s1 * (1.0f / 64.0f);
        float v0 = 0.f, v1 = 0.f;
#pragma unroll
        for (int nt = 0; nt < 8; ++nt) {
            float d0 = acc[nt][0] - mu0, d1 = acc[nt][1] - mu0;
            float d2 = acc[nt][2] - mu1, d3 = acc[nt][3] - mu1;
            v0 += d0 * d0 + d1 * d1;
            v1 += d2 * d2 + d3 * d3;
        }
        v0 += __shfl_xor_sync(0xffffffffu, v0, 1);
        v0 += __shfl_xor_sync(0xffffffffu, v0, 2);
        v1 += __shfl_xor_sync(0xffffffffu, v1, 1);
        v1 += __shfl_xor_sync(0xffffffffu, v1, 2);
        float r0 = rsqrtf(v0 * (1.0f / 64.0f) + 1e-5f);
        float r1 = rsqrtf(v1 * (1.0f / 64.0f) + 1e-5f);

        __nv_bfloat16* y0 = g_Yb + (base_tok + rr) * (long)CDd + k * 64;
        __nv_bfloat16* y1 = y0 + 8 * (long)CDd;
#pragma unroll
        for (int nt = 0; nt < 8; ++nt) {
            int col = nt * 8 + 2 * q;
            float2 cgv = *(const float2*)&CG[col];
            float2 cbv = *(const float2*)&CB[col];
            unsigned p0 = pk_bf16x2((acc[nt][0] - mu0) * r0 * cgv.x + cbv.x,
                                    (acc[nt][1] - mu0) * r0 * cgv.y + cbv.y);
            unsigned p1 = pk_bf16x2((acc[nt][2] - mu1) * r1 * cgv.x + cbv.x,
                                    (acc[nt][3] - mu1) * r1 * cgv.y + cbv.y);
            *(unsigned*)(y0 + col) = p0;
            *(unsigned*)(y1 + col) = p1;
        }
    }
}

// ================= K2: bf16 HMMA projection GEMM + gated residual (proven config) =================
#define PSM_TOTAL 68608

__global__ void __launch_bounds__(256)
proj_kernel(const float* __restrict__ bp, const float* __restrict__ x, float* __restrict__ out)
{
    extern __shared__ char psm[];
    const unsigned sbase = (unsigned)__cvta_generic_to_shared(psm);
    const unsigned sA = sbase;
    const unsigned sB = sbase + 32768;
    float* smf = (float*)psm;
    const int tid = threadIdx.x, lane = tid & 31, wid = tid >> 5;
    const int wm = wid & 1, wn = wid >> 1;      // 2M x 4N
    const long m0 = (long)blockIdx.y * 128;
    const int n0 = blockIdx.x * 128;

    float acc[4][4][4];
#pragma unroll
    for (int mt = 0; mt < 4; ++mt)
#pragma unroll
        for (int nt = 0; nt < 4; ++nt)
#pragma unroll
            for (int c = 0; c < 4; ++c) acc[mt][nt][c] = 0.f;

    const int ar = tid >> 3, acq = tid & 7;
    const int br = tid >> 4, bcq = tid & 15;
    const __nv_bfloat16* Agbase = g_Yb + (m0 + ar) * (long)CDd + acq * 8;
    const __nv_bfloat16* Bgbase = g_Wpb + (long)br * Dd + n0 + bcq * 8;

    auto loadTile = [&](int kc, int buf) {
        unsigned Ab = sA + buf * 16384;
        unsigned Bb = sB + buf * 16384;
        const __nv_bfloat16* Ag = Agbase + kc * 64;
        const __nv_bfloat16* Bg = Bgbase + (long)(kc * 64) * Dd;
#pragma unroll
        for (int i = 0; i < 4; ++i) {
            int r = ar + i * 32;
            unsigned off = (unsigned)(r * 128 + acq * 16);
            cpa16(Ab + (off ^ ((r & 7) << 4)), Ag + (long)i * 32 * CDd);
        }
#pragma unroll
        for (int i = 0; i < 4; ++i) {
            int r = br + i * 16;
            unsigned off = (unsigned)(r * 256 + bcq * 16);
            cpa16(Bb + (off ^ ((r & 7) << 4)), Bg + (long)i * 16 * Dd);
        }
    };

    loadTile(0, 0);
    CP_COMMIT();

    const unsigned sw = (unsigned)((lane & 7) << 4);
    const int al = lane & 15, ah = lane >> 4;

    for (int kc = 0; kc < 8; ++kc) {
        CP_WAIT0();
        __syncthreads();
        if (kc + 1 < 8) { loadTile(kc + 1, (kc + 1) & 1); CP_COMMIT(); }

        unsigned Ab = sA + (kc & 1) * 16384;
        unsigned Bb = sB + (kc & 1) * 16384;
#pragma unroll
        for (int ks = 0; ks < 4; ++ks) {
            unsigned afr[4][4];
#pragma unroll
            for (int mt = 0; mt < 4; ++mt) {
                unsigned row = wm * 64 + mt * 16 + al;
                unsigned off = row * 128 + ks * 32 + ah * 16;
                ldm_x4(afr[mt], Ab + (off ^ sw));
            }
            unsigned bfr[2][4];
#pragma unroll
            for (int nq = 0; nq < 2; ++nq) {
                unsigned row = ks * 16 + al;
                unsigned off = row * 256 + (wn * 32 + nq * 16 + ah * 8) * 2;
                ldm_x4_t(bfr[nq], Bb + (off ^ sw));
            }
#pragma unroll
            for (int mt = 0; mt < 4; ++mt)
#pragma unroll
                for (int nq = 0; nq < 2; ++nq) {
                    mma_bf16(acc[mt][2 * nq],     afr[mt], bfr[nq][0], bfr[nq][1]);
                    mma_bf16(acc[mt][2 * nq + 1], afr[mt], bfr[nq][2], bfr[nq][3]);
                }
        }
        __syncthreads();
    }

    // stage accumulators to smem [128][132]
#pragma unroll
    for (int mt = 0; mt < 4; ++mt) {
        int r0 = wm * 64 + mt * 16 + (lane >> 2);
#pragma unroll
        for (int nt = 0; nt < 4; ++nt) {
            int c = wn * 32 + nt * 8 + 2 * (lane & 3);
            *(float2*)&smf[r0 * 132 + c]       = make_float2(acc[mt][nt][0], acc[mt][nt][1]);
            *(float2*)&smf[(r0 + 8) * 132 + c] = make_float2(acc[mt][nt][2], acc[mt][nt][3]);
        }
    }
    __syncthreads();

    // coalesced gated-residual epilogue
    const int cc = lane * 4;
    float4 gs  = *(const float4*)&g_gatesig[n0 + cc];
    float4 bpv = *(const float4*)(bp + n0 + cc);
#pragma unroll
    for (int it = 0; it < 16; ++it) {
        int rr = it * 8 + wid;
        float4 v = *(float4*)&smf[rr * 132 + cc];
        const float* xr = x + (m0 + rr) * (long)Dd + n0 + cc;
        float4 xv = *(const float4*)xr;
        float4 o;
        o.x = xv.x + gs.x * (v.x + bpv.x);
        o.y = xv.y + gs.y * (v.y + bpv.y);
        o.z = xv.z + gs.z * (v.z + bpv.z);
        o.w = xv.w + gs.w * (v.w + bpv.w);
        *(float4*)(out + (m0 + rr) * (long)Dd + n0 + cc) = o;
    }
}

// ================= launch =================
extern "C" void kernel_launch(void* const* d_in, const int* in_sizes, int n_in,
                              void* d_out, int out_size) {
    const float* x       = (const float*)d_in[0];
    const float* anchors = (const float*)d_in[1];
    const float* ln_g    = (const float*)d_in[2];
    const float* ln_b    = (const float*)d_in[3];
    const float* W1      = (const float*)d_in[4];
    const float* b1      = (const float*)d_in[5];
    const float* W2      = (const float*)d_in[6];
    const float* b2      = (const float*)d_in[7];
    const float* cg      = (const float*)d_in[8];
    const float* cb      = (const float*)d_in[9];
    const float* Wp      = (const float*)d_in[10];
    const float* bp      = (const float*)d_in[11];
    const float* gate    = (const float*)d_in[12];
    float* out = (float*)d_out;

    const int Ntok = in_sizes[0] / Dd;   // 32768

    cudaFuncSetAttribute(token_kernel, cudaFuncAttributeMaxDynamicSharedMemorySize,
                         SM_FLOATS * sizeof(float));
    cudaFuncSetAttribute(proj_kernel, cudaFuncAttributeMaxDynamicSharedMemorySize, PSM_TOTAL);

    prep_kernel<<<64 + 1 + Cc + 1, 256>>>(anchors, gate, Wp, W2);
    token_kernel<<<Ntok / TB, 256, SM_FLOATS * sizeof(float)>>>(
        x, ln_g, ln_b, W1, b1, b2, cg, cb);
    proj_kernel<<<dim3(Dd / 128, Ntok / 128), 256, PSM_TOTAL>>>(bp, x, out);
}